// round 14
// baseline (speedup 1.0000x reference)
#include <cuda_runtime.h>
#include <cuda_bf16.h>
#include <math.h>
#include <stdint.h>

#define LNUM 4
#define DMODEL 512
#define HEADS 8
#define DKH 256
#define DFFN 2048
#define BB 8
#define SS 256
#define HD (HEADS*DKH)          // 2048
#define TOK (BB*SS)             // 2048
#define QKVN (3*HD)             // 6144
#define EPS 1e-6f

// ---------------- scratch (device globals; no allocations) ----------------
__device__ float g_x [TOK*DMODEL];          // fp32 residual stream

__device__ __nv_bfloat16 g_x2b [TOK*DMODEL];
__device__ __nv_bfloat16 g_qkv [TOK*QKVN];  // packed q|k|v
__device__ __nv_bfloat16 g_ob  [TOK*HD];
__device__ __nv_bfloat16 g_fb  [TOK*DFFN];
// bf16 weights
#define WSZ 4194304                          // 4*512*2048
__device__ __nv_bfloat16 g_wqkv[LNUM*DMODEL*QKVN];   // packed per-layer [512][6144]
__device__ float         g_bqkv[LNUM*QKVN];
__device__ __nv_bfloat16 g_wo[WSZ];
__device__ __nv_bfloat16 g_w1[WSZ];
__device__ __nv_bfloat16 g_w2[WSZ];

// ---------------- PTX helpers ---------------------------------------------
__device__ __forceinline__ void cpa16(uint32_t dst, const void* src) {
    asm volatile("cp.async.cg.shared.global [%0], [%1], 16;" :: "r"(dst), "l"(src) : "memory");
}
__device__ __forceinline__ void cp_commit() {
    asm volatile("cp.async.commit_group;" ::: "memory");
}
template<int N>
__device__ __forceinline__ void cp_wait() {
    asm volatile("cp.async.wait_group %0;" :: "n"(N) : "memory");
}
__device__ __forceinline__ void ldsm4(uint32_t& r0, uint32_t& r1, uint32_t& r2, uint32_t& r3, uint32_t a) {
    asm volatile("ldmatrix.sync.aligned.m8n8.x4.shared.b16 {%0,%1,%2,%3}, [%4];"
                 : "=r"(r0), "=r"(r1), "=r"(r2), "=r"(r3) : "r"(a));
}
__device__ __forceinline__ void ldsm4t(uint32_t& r0, uint32_t& r1, uint32_t& r2, uint32_t& r3, uint32_t a) {
    asm volatile("ldmatrix.sync.aligned.m8n8.x4.trans.shared.b16 {%0,%1,%2,%3}, [%4];"
                 : "=r"(r0), "=r"(r1), "=r"(r2), "=r"(r3) : "r"(a));
}
__device__ __forceinline__ void mma_bf16(float* d, const uint32_t* a, const uint32_t* b) {
    asm volatile("mma.sync.aligned.m16n8k16.row.col.f32.bf16.bf16.f32 "
                 "{%0,%1,%2,%3}, {%4,%5,%6,%7}, {%8,%9}, {%0,%1,%2,%3};"
                 : "+f"(d[0]), "+f"(d[1]), "+f"(d[2]), "+f"(d[3])
                 : "r"(a[0]), "r"(a[1]), "r"(a[2]), "r"(a[3]), "r"(b[0]), "r"(b[1]));
}

// ---------------- weight fp32 -> bf16 (once per launch) -------------------
__global__ void cvt_weights(const float* __restrict__ wq, const float* __restrict__ wk,
                            const float* __restrict__ wv, const float* __restrict__ wo,
                            const float* __restrict__ w1, const float* __restrict__ w2)
{
    long i4 = (long)blockIdx.x * blockDim.x + threadIdx.x;
    int which = (int)(i4 >> 20);
    long off = (i4 & ((1L << 20) - 1)) << 2;
    const float* s;
    __nv_bfloat16* d;
    long doff = off;
    if (which < 3) {
        s = (which == 0) ? wq : (which == 1) ? wk : wv;
        long l   = off / ((long)DMODEL * HD);
        long win = off - l * (long)DMODEL * HD;
        long row = win / HD;
        long col = win - row * HD;
        d = g_wqkv;
        doff = l * (long)DMODEL * QKVN + row * QKVN + which * HD + col;
    } else {
        s = (which == 3) ? wo : (which == 4) ? w1 : w2;
        d = (which == 3) ? g_wo : (which == 4) ? g_w1 : g_w2;
    }
    float4 v = *(const float4*)(s + off);
    *(__nv_bfloat162*)(d + doff)     = __floats2bfloat162_rn(v.x, v.y);
    *(__nv_bfloat162*)(d + doff + 2) = __floats2bfloat162_rn(v.z, v.w);
}

__global__ void cvt_bias(const float* __restrict__ bq, const float* __restrict__ bk,
                         const float* __restrict__ bv)
{
    int idx = blockIdx.x * blockDim.x + threadIdx.x;
    if (idx >= LNUM * QKVN) return;
    int l = idx / QKVN;
    int c = idx - l * QKVN;
    int which = c >> 11;
    int col = c & (HD - 1);
    const float* s = (which == 0) ? bq : (which == 1) ? bk : bv;
    g_bqkv[idx] = s[l * HD + col];
}

// ---------------- embed ----------------------------------------------------
__global__ void embed_kernel(const float* __restrict__ data,
                             const float* __restrict__ seg_emb,
                             const int* __restrict__ view,
                             float* __restrict__ x)
{
    int idx = blockIdx.x * blockDim.x + threadIdx.x;
    if (idx >= TOK * DMODEL) return;
    int c = idx & (DMODEL - 1);
    int s = (idx >> 9) & (SS - 1);
    float inv = exp2f(-(float)c * (1.0f / 32.0f));
    float arg = (float)s * inv;
    float pe  = (c & 1) ? cosf(arg) : sinf(arg);
    int seg_off = view[0] * SS * DMODEL + c;
    x[idx] = data[idx] * sqrtf((float)DMODEL) + pe + seg_emb[seg_off];
}

// ---------------- layernorm: warp handles 2 rows ---------------------------
template<bool OB>
__global__ void layernorm_kernel(const float* __restrict__ x,
                                 const float* __restrict__ alpha,
                                 const float* __restrict__ beta,
                                 float* __restrict__ outf,
                                 __nv_bfloat16* __restrict__ outb)
{
    const int wid = threadIdx.x >> 5, lane = threadIdx.x & 31;
    const int row0 = blockIdx.x * 16 + wid * 2;

    float4 v[2][4];
    float s[2] = {0.f, 0.f}, sq[2] = {0.f, 0.f};
    #pragma unroll
    for (int r = 0; r < 2; r++) {
        const float4* p4 = (const float4*)(x + (long)(row0 + r) * DMODEL);
        #pragma unroll
        for (int j = 0; j < 4; j++) {
            v[r][j] = p4[lane + j * 32];
            s[r]  += v[r][j].x + v[r][j].y + v[r][j].z + v[r][j].w;
            sq[r] += v[r][j].x * v[r][j].x + v[r][j].y * v[r][j].y
                   + v[r][j].z * v[r][j].z + v[r][j].w * v[r][j].w;
        }
    }
    #pragma unroll
    for (int off = 16; off > 0; off >>= 1) {
        s[0]  += __shfl_xor_sync(0xffffffff, s[0],  off);
        sq[0] += __shfl_xor_sync(0xffffffff, sq[0], off);
        s[1]  += __shfl_xor_sync(0xffffffff, s[1],  off);
        sq[1] += __shfl_xor_sync(0xffffffff, sq[1], off);
    }

    const float4* a4 = (const float4*)alpha;
    const float4* b4 = (const float4*)beta;
    #pragma unroll
    for (int r = 0; r < 2; r++) {
        float mean = s[r] * (1.0f / DMODEL);
        float var  = (sq[r] - (float)DMODEL * mean * mean) * (1.0f / (DMODEL - 1));
        var = fmaxf(var, 0.f);
        float rinv = 1.0f / (sqrtf(var) + EPS);
        #pragma unroll
        for (int j = 0; j < 4; j++) {
            float4 av = a4[lane + j * 32];
            float4 bv = b4[lane + j * 32];
            float ox = av.x * (v[r][j].x - mean) * rinv + bv.x;
            float oy = av.y * (v[r][j].y - mean) * rinv + bv.y;
            float oz = av.z * (v[r][j].z - mean) * rinv + bv.z;
            float ow = av.w * (v[r][j].w - mean) * rinv + bv.w;
            long e = (long)(row0 + r) * DMODEL + (lane + j * 32) * 4;
            if (OB) {
                *(__nv_bfloat162*)(outb + e)     = __floats2bfloat162_rn(ox, oy);
                *(__nv_bfloat162*)(outb + e + 2) = __floats2bfloat162_rn(oz, ow);
            } else {
                *(float4*)(outf + e) = make_float4(ox, oy, oz, ow);
            }
        }
    }
}

// ---------------- fused attention: QK^T + mask + softmax + PV -------------
#define ATT_NST 4
#define ATT_SMEM_BYTES 139264
#define ATT_P_ELOFF    0
#define ATT_V_ELOFF    33792
#define ATT_PMAX_BOFF  135168
#define ATT_PSUM_BOFF  137216

__global__ void __launch_bounds__(256)
attn_fused(const __nv_bfloat16* __restrict__ qkv,
           const int* __restrict__ attn_m,
           __nv_bfloat16* __restrict__ ob)
{
    extern __shared__ __align__(16) char smem_raw[];
    __nv_bfloat16* As = (__nv_bfloat16*)smem_raw;
    __nv_bfloat16* Bs = As + ATT_NST * 128 * 40;
    __nv_bfloat16* Ps = (__nv_bfloat16*)smem_raw + ATT_P_ELOFF;
    __nv_bfloat16* Vs = (__nv_bfloat16*)smem_raw + ATT_V_ELOFF;
    float* pmax = (float*)(smem_raw + ATT_PMAX_BOFF);
    float* psum = (float*)(smem_raw + ATT_PSUM_BOFF);
    __shared__ int msk[SS];

    const int z = blockIdx.y;
    const int b = z >> 3, h = z & 7;
    const int m0 = blockIdx.x << 7;
    const long sQb = (long)SS * QKVN;
    const __nv_bfloat16* A = qkv + b * sQb + (long)h * DKH + (long)m0 * QKVN;
    const __nv_bfloat16* K = qkv + HD + b * sQb + (long)h * DKH;
    const __nv_bfloat16* V = qkv + 2 * HD + b * sQb + (long)h * DKH;

    const int tid  = threadIdx.x;
    const int wid  = tid >> 5;
    const int lane = tid & 31;
    const int mbase = (wid >> 2) * 64;
    const int nbase = (wid & 3) * 64;
    const int wn = wid & 3;
    const int lr  = ((lane >> 3) & 1) * 8 + (lane & 7);
    const int lc8 = (lane >> 4) * 8;
    const int lg = lane >> 2, lt = lane & 3;

    if (tid < SS) msk[tid] = attn_m[b * SS + tid];

    uint32_t sAs = (uint32_t)__cvta_generic_to_shared(As);
    uint32_t sBs = (uint32_t)__cvta_generic_to_shared(Bs);
    uint32_t sPs = (uint32_t)__cvta_generic_to_shared(Ps);
    uint32_t sVs = (uint32_t)__cvta_generic_to_shared(Vs);

    float acc[4][8][4];
    #pragma unroll
    for (int i = 0; i < 4; i++)
        #pragma unroll
        for (int j = 0; j < 8; j++)
            #pragma unroll
            for (int r = 0; r < 4; r++) acc[i][j][r] = 0.f;

    auto stageQK = [&](int s, int kb) {
        #pragma unroll
        for (int t = 0; t < 2; t++) {
            int idx = tid + t * 256;
            int row = idx >> 2, ck = idx & 3;
            uint32_t d = sAs + 2u * ((s * 128 + row) * 40 + ck * 8);
            cpa16(d, A + (long)row * QKVN + kb + ck * 8);
        }
        #pragma unroll
        for (int t = 0; t < 4; t++) {
            int idx = tid + t * 256;
            int row = idx >> 2, ck = idx & 3;
            uint32_t d = sBs + 2u * ((s * 256 + row) * 40 + ck * 8);
            cpa16(d, K + (long)row * QKVN + kb + ck * 8);
        }
    };

    const int NIT = DKH / 32;     // 8
    stageQK(0, 0);  cp_commit();
    stageQK(1, 32); cp_commit();
    stageQK(2, 64); cp_commit();

    for (int it = 0; it < NIT; it++) {
        int s = it & 3;
        cp_wait<2>();
        __syncthreads();

        #pragma unroll
        for (int ks = 0; ks < 32; ks += 16) {
            uint32_t a[4][4], bf[8][2];
            #pragma unroll
            for (int i = 0; i < 4; i++) {
                uint32_t addr = sAs + 2u * ((s * 128 + mbase + i * 16 + lr) * 40 + ks + lc8);
                ldsm4(a[i][0], a[i][1], a[i][2], a[i][3], addr);
            }
            #pragma unroll
            for (int jb = 0; jb < 4; jb++) {
                uint32_t r0, r1, r2, r3;
                uint32_t addr = sBs + 2u * ((s * 256 + nbase + jb * 16 + lr) * 40 + ks + lc8);
                ldsm4(r0, r1, r2, r3, addr);
                bf[jb * 2 + 0][0] = r0; bf[jb * 2 + 0][1] = r2;
                bf[jb * 2 + 1][0] = r1; bf[jb * 2 + 1][1] = r3;
            }
            #pragma unroll
            for (int i = 0; i < 4; i++)
                #pragma unroll
                for (int j = 0; j < 8; j++)
                    mma_bf16(acc[i][j], a[i], bf[j]);
        }

        if (it + 3 < NIT) stageQK((it + 3) & 3, (it + 3) << 5);
        cp_commit();
    }
    cp_wait<0>();
    __syncthreads();

    auto stageV = [&](int s, int k0) {
        #pragma unroll
        for (int t = 0; t < 4; t++) {
            int idx = tid + t * 256;
            int row = idx >> 5, c8 = idx & 31;
            uint32_t d = sVs + 2u * ((s * 32 + row) * 264 + c8 * 8);
            cpa16(d, V + (long)(k0 + row) * QKVN + c8 * 8);
        }
    };
    stageV(0, 0);  cp_commit();
    stageV(1, 32); cp_commit();
    stageV(2, 64); cp_commit();

    #pragma unroll
    for (int i = 0; i < 4; i++) {
        float m0v = -1e30f, m1v = -1e30f;
        #pragma unroll
        for (int j = 0; j < 8; j++) {
            int c0 = nbase + j * 8 + lt * 2;
            bool k0 = msk[c0] != 0, k1 = msk[c0 + 1] != 0;
            acc[i][j][0] = k0 ? -1e9f : acc[i][j][0] * 0.0625f;
            acc[i][j][1] = k1 ? -1e9f : acc[i][j][1] * 0.0625f;
            acc[i][j][2] = k0 ? -1e9f : acc[i][j][2] * 0.0625f;
            acc[i][j][3] = k1 ? -1e9f : acc[i][j][3] * 0.0625f;
            m0v = fmaxf(m0v, fmaxf(acc[i][j][0], acc[i][j][1]));
            m1v = fmaxf(m1v, fmaxf(acc[i][j][2], acc[i][j][3]));
        }
        m0v = fmaxf(m0v, __shfl_xor_sync(0xffffffff, m0v, 1));
        m0v = fmaxf(m0v, __shfl_xor_sync(0xffffffff, m0v, 2));
        m1v = fmaxf(m1v, __shfl_xor_sync(0xffffffff, m1v, 1));
        m1v = fmaxf(m1v, __shfl_xor_sync(0xffffffff, m1v, 2));
        if (lt == 0) {
            pmax[(mbase + i * 16 + lg) * 4 + wn]     = m0v;
            pmax[(mbase + i * 16 + 8 + lg) * 4 + wn] = m1v;
        }
    }
    __syncthreads();

    float rinv0[4], rinv1[4];
    #pragma unroll
    for (int i = 0; i < 4; i++) {
        int r0 = mbase + i * 16 + lg;
        const float* px0 = pmax + r0 * 4;
        const float* px1 = pmax + (r0 + 8) * 4;
        float g0 = fmaxf(fmaxf(px0[0], px0[1]), fmaxf(px0[2], px0[3]));
        float g1 = fmaxf(fmaxf(px1[0], px1[1]), fmaxf(px1[2], px1[3]));
        float s0 = 0.f, s1 = 0.f;
        #pragma unroll
        for (int j = 0; j < 8; j++) {
            acc[i][j][0] = expf(acc[i][j][0] - g0);
            acc[i][j][1] = expf(acc[i][j][1] - g0);
            acc[i][j][2] = expf(acc[i][j][2] - g1);
            acc[i][j][3] = expf(acc[i][j][3] - g1);
            s0 += acc[i][j][0] + acc[i][j][1];
            s1 += acc[i][j][2] + acc[i][j][3];
        }
        s0 += __shfl_xor_sync(0xffffffff, s0, 1);
        s0 += __shfl_xor_sync(0xffffffff, s0, 2);
        s1 += __shfl_xor_sync(0xffffffff, s1, 1);
        s1 += __shfl_xor_sync(0xffffffff, s1, 2);
        if (lt == 0) {
            psum[r0 * 4 + wn]       = s0;
            psum[(r0 + 8) * 4 + wn] = s1;
        }
    }
    __syncthreads();

    #pragma unroll
    for (int i = 0; i < 4; i++) {
        int r0 = mbase + i * 16 + lg;
        const float* ps0 = psum + r0 * 4;
        const float* ps1 = psum + (r0 + 8) * 4;
        rinv0[i] = 1.0f / (ps0[0] + ps0[1] + ps0[2] + ps0[3]);
        rinv1[i] = 1.0f / (ps1[0] + ps1[1] + ps1[2] + ps1[3]);
        #pragma unroll
        for (int j = 0; j < 8; j++) {
            int c0 = nbase + j * 8 + lt * 2;
            *(__nv_bfloat162*)(Ps + (r0 * 264 + c0)) =
                __floats2bfloat162_rn(acc[i][j][0] * rinv0[i], acc[i][j][1] * rinv0[i]);
            *(__nv_bfloat162*)(Ps + ((r0 + 8) * 264 + c0)) =
                __floats2bfloat162_rn(acc[i][j][2] * rinv1[i], acc[i][j][3] * rinv1[i]);
        }
    }

    #pragma unroll
    for (int i = 0; i < 4; i++)
        #pragma unroll
        for (int j = 0; j < 8; j++)
            #pragma unroll
            for (int r = 0; r < 4; r++) acc[i][j][r] = 0.f;

    for (int it = 0; it < 8; it++) {
        int s = it & 3;
        cp_wait<2>();
        __syncthreads();

        #pragma unroll
        for (int ks = 0; ks < 32; ks += 16) {
            int kg = it * 32 + ks;
            uint32_t a[4][4], bf[8][2];
            #pragma unroll
            for (int i = 0; i < 4; i++) {
                uint32_t addr = sPs + 2u * ((mbase + i * 16 + lr) * 264 + kg + lc8);
                ldsm4(a[i][0], a[i][1], a[i][2], a[i][3], addr);
            }
            #pragma unroll
            for (int jb = 0; jb < 4; jb++) {
                uint32_t r0, r1, r2, r3;
                uint32_t addr = sVs + 2u * ((s * 32 + ks + lr) * 264 + nbase + jb * 16 + lc8);
                ldsm4t(r0, r1, r2, r3, addr);
                bf[jb * 2 + 0][0] = r0; bf[jb * 2 + 0][1] = r1;
                bf[jb * 2 + 1][0] = r2; bf[jb * 2 + 1][1] = r3;
            }
            #pragma unroll
            for (int i = 0; i < 4; i++)
                #pragma unroll
                for (int j = 0; j < 8; j++)
                    mma_bf16(acc[i][j], a[i], bf[j]);
        }

        if (it + 3 < 8) stageV((it + 3) & 3, (it + 3) << 5);
        cp_commit();
    }

    #pragma unroll
    for (int i = 0; i < 4; i++) {
        int r0 = mbase + i * 16 + lg;
        long base0 = (long)(b * SS + m0 + r0) * HD + h * DKH;
        long base1 = (long)(b * SS + m0 + r0 + 8) * HD + h * DKH;
        #pragma unroll
        for (int j = 0; j < 8; j++) {
            int c0 = nbase + j * 8 + lt * 2;
            *(__nv_bfloat162*)(ob + base0 + c0) =
                __floats2bfloat162_rn(acc[i][j][0], acc[i][j][1]);
            *(__nv_bfloat162*)(ob + base1 + c0) =
                __floats2bfloat162_rn(acc[i][j][2], acc[i][j][3]);
        }
    }
}

// ---------------- bf16 HMMA GEMM 128x256, BK=64, 3-stage (QKV / FFN1) -----
// C[M,N] = A[M,K] @ B[K,N] + bias (+relu), bf16 out. N tile 256 (264 pad).
#define G256_SMEM ((3*128*72 + 3*64*264) * 2)      // 156672
template<bool RELU>
__global__ void __launch_bounds__(256)
gemm_bf256(const __nv_bfloat16* __restrict__ A, const __nv_bfloat16* __restrict__ B,
           const float* __restrict__ bias, __nv_bfloat16* __restrict__ C,
           int K, int lda, int ldb, int ldc)
{
    extern __shared__ __align__(16) char smem_raw[];
    __nv_bfloat16* As = (__nv_bfloat16*)smem_raw;            // [3][128][72]
    __nv_bfloat16* Bs = As + 3 * 128 * 72;                   // [3][64][264]

    const int m0 = blockIdx.y << 7, n0 = blockIdx.x << 8;
    const int tid  = threadIdx.x;
    const int wid  = tid >> 5;
    const int lane = tid & 31;
    const int mbase = (wid >> 2) * 64;
    const int nbase = (wid & 3) * 64;
    const int lr  = ((lane >> 3) & 1) * 8 + (lane & 7);
    const int lc8 = (lane >> 4) * 8;

    uint32_t sAs = (uint32_t)__cvta_generic_to_shared(As);
    uint32_t sBs = (uint32_t)__cvta_generic_to_shared(Bs);

    float acc[4][8][4];
    #pragma unroll
    for (int i = 0; i < 4; i++)
        #pragma unroll
        for (int j = 0; j < 8; j++)
            #pragma unroll
            for (int r = 0; r < 4; r++) acc[i][j][r] = 0.f;

    auto stage = [&](int s, int kb) {
        #pragma unroll
        for (int t = 0; t < 4; t++) {               // A: 128 x 64 = 1024 chunks
            int idx = tid + t * 256;
            int row = idx >> 3, ck = idx & 7;
            uint32_t d = sAs + 2u * ((s * 128 + row) * 72 + ck * 8);
            cpa16(d, A + (long)(m0 + row) * lda + kb + ck * 8);
        }
        #pragma unroll
        for (int t = 0; t < 8; t++) {               // B: 64 x 256 = 2048 chunks
            int idx = tid + t * 256;
            int row = idx >> 5, c8 = idx & 31;
            uint32_t d = sBs + 2u * ((s * 64 + row) * 264 + c8 * 8);
            cpa16(d, B + (long)(kb + row) * ldb + n0 + c8 * 8);
        }
    };

    const int NIT = K >> 6;      // K=512 -> 8
    stage(0, 0);  cp_commit();
    stage(1, 64); cp_commit();

    for (int it = 0; it < NIT; it++) {
        int s = it % 3;
        cp_wait<1>();
        __syncthreads();

        #pragma unroll
        for (int ks = 0; ks < 64; ks += 16) {
            uint32_t a[4][4], bf[8][2];
            #pragma unroll
            for (int i = 0; i < 4; i++) {
                uint32_t addr = sAs + 2u * ((s * 128 + mbase + i * 16 + lr) * 72 + ks + lc8);
                ldsm4(a[i][0], a[i][1], a[i][2], a[i][3], addr);
            }
            #pragma unroll
            for (int jb = 0; jb < 4; jb++) {
                uint32_t r0, r1, r2, r3;
                uint32_t addr = sBs + 2u * ((s * 64 + ks + lr) * 264 + nbase + jb * 16 + lc8);
                ldsm4t(r0, r1, r2, r3, addr);
                bf[jb * 2 + 0][0] = r0; bf[jb * 2 + 0][1] = r1;
                bf[jb * 2 + 1][0] = r2; bf[jb * 2 + 1][1] = r3;
            }
            #pragma unroll
            for (int i = 0; i < 4; i++)
                #pragma unroll
                for (int j = 0; j < 8; j++)
                    mma_bf16(acc[i][j], a[i], bf[j]);
        }

        if (it + 2 < NIT) stage((it + 2) % 3, (it + 2) << 6);
        cp_commit();
    }

    #pragma unroll
    for (int i = 0; i < 4; i++) {
        int r0 = m0 + mbase + i * 16 + (lane >> 2);
        #pragma unroll
        for (int j = 0; j < 8; j++) {
            int c0 = n0 + nbase + j * 8 + (lane & 3) * 2;
            float b0 = bias[c0], b1 = bias[c0 + 1];
            float v00 = acc[i][j][0] + b0, v01 = acc[i][j][1] + b1;
            float v10 = acc[i][j][2] + b0, v11 = acc[i][j][3] + b1;
            if (RELU) {
                v00 = fmaxf(v00, 0.f); v01 = fmaxf(v01, 0.f);
                v10 = fmaxf(v10, 0.f); v11 = fmaxf(v11, 0.f);
            }
            *(__nv_bfloat162*)(C + (long)r0 * ldc + c0) = __floats2bfloat162_rn(v00, v01);
            *(__nv_bfloat162*)(C + (long)(r0 + 8) * ldc + c0) = __floats2bfloat162_rn(v10, v11);
        }
    }
}

// ---------------- bf16 HMMA GEMM (Wo/W2), BK=64, 3-stage cp.async ---------
#define NSTAGE 3
template<int BM, bool TB>
struct SmemCfg {
    static constexpr int AROW  = 72;
    static constexpr int BROWS = TB ? 128 : 64;
    static constexpr int BCOLS = TB ? 72 : 136;
    static constexpr int A_ELEMS = NSTAGE * BM * AROW;
    static constexpr int B_ELEMS = NSTAGE * BROWS * BCOLS;
    static constexpr int BYTES = (A_ELEMS + B_ELEMS) * 2;
};

template<int BM, bool TB, bool RELU, bool RES, bool OUTBF>
__global__ void __launch_bounds__(256)
gemm_bf(const __nv_bfloat16* __restrict__ A, const __nv_bfloat16* __restrict__ B,
        const float* __restrict__ bias, const float* __restrict__ res,
        float* __restrict__ Cf, __nv_bfloat16* __restrict__ Cb,
        int K, int lda, int ldb, int ldc,
        long sAb, long sAh, long sBb, long sBh, long sCb, long sCh)
{
    constexpr int IT = BM / 32;

    extern __shared__ __align__(16) char smem_raw[];
    __nv_bfloat16* As = (__nv_bfloat16*)smem_raw;
    __nv_bfloat16* Bs = As + SmemCfg<BM,TB>::A_ELEMS;

    int z = blockIdx.z;
    int bb = z >> 3, hh = z & 7;
    A += bb * sAb + hh * sAh;
    B += bb * sBb + hh * sBh;
    if (RES) res += bb * sCb + hh * sCh;
    long cbase = bb * sCb + hh * sCh;

    const int m0 = blockIdx.y * BM, n0 = blockIdx.x << 7;
    const int tid  = threadIdx.x;
    const int wid  = tid >> 5;
    const int lane = tid & 31;
    const int mbase = (wid >> 2) * (BM / 2);
    const int nbase = (wid & 3) * 32;
    const int lr  = ((lane >> 3) & 1) * 8 + (lane & 7);
    const int lc8 = (lane >> 4) * 8;

    uint32_t sAs = (uint32_t)__cvta_generic_to_shared(As);
    uint32_t sBs = (uint32_t)__cvta_generic_to_shared(Bs);

    float acc[IT][4][4];
    #pragma unroll
    for (int i = 0; i < IT; i++)
        #pragma unroll
        for (int j = 0; j < 4; j++)
            #pragma unroll
            for (int r = 0; r < 4; r++) acc[i][j][r] = 0.f;

    auto stage = [&](int s, int kb) {
        #pragma unroll
        for (int t = 0; t < BM / 32; t++) {
            int idx = tid + t * 256;
            int row = idx >> 3, ck = idx & 7;
            uint32_t d = sAs + 2u * ((s * BM + row) * 72 + ck * 8);
            cpa16(d, A + (long)(m0 + row) * lda + kb + ck * 8);
        }
        if (!TB) {
            #pragma unroll
            for (int t = 0; t < 4; t++) {
                int idx = tid + t * 256;
                int row = idx >> 4, ck = idx & 15;
                uint32_t d = sBs + 2u * ((s * 64 + row) * 136 + ck * 8);
                cpa16(d, B + (long)(kb + row) * ldb + n0 + ck * 8);
            }
        } else {
            #pragma unroll
            for (int t = 0; t < 4; t++) {
                int idx = tid + t * 256;
                int row = idx >> 3, ck = idx & 7;
                uint32_t d = sBs + 2u * ((s * 128 + row) * 72 + ck * 8);
                cpa16(d, B + (long)(n0 + row) * ldb + kb + ck * 8);
            }
        }
    };

    const int NIT = K >> 6;
    stage(0, 0);  cp_commit();
    stage(1, 64); cp_commit();

    for (int it = 0; it < NIT; it++) {
        int s = it % 3;
        cp_wait<1>();
        __syncthreads();

        #pragma unroll
        for (int ks = 0; ks < 64; ks += 16) {
            uint32_t a[IT][4], bf[4][2];
            #pragma unroll
            for (int i = 0; i < IT; i++) {
                uint32_t addr = sAs + 2u * ((s * BM + mbase + i * 16 + lr) * 72 + ks + lc8);
                ldsm4(a[i][0], a[i][1], a[i][2], a[i][3], addr);
            }
            #pragma unroll
            for (int jb = 0; jb < 2; jb++) {
                uint32_t r0, r1, r2, r3;
                if (!TB) {
                    uint32_t addr = sBs + 2u * ((s * 64 + ks + lr) * 136 + nbase + jb * 16 + lc8);
                    ldsm4t(r0, r1, r2, r3, addr);
                    bf[jb * 2 + 0][0] = r0; bf[jb * 2 + 0][1] = r1;
                    bf[jb * 2 + 1][0] = r2; bf[jb * 2 + 1][1] = r3;
                } else {
                    uint32_t addr = sBs + 2u * ((s * 128 + nbase + jb * 16 + lr) * 72 + ks + lc8);
                    ldsm4(r0, r1, r2, r3, addr);
                    bf[jb * 2 + 0][0] = r0; bf[jb * 2 + 0][1] = r2;
                    bf[jb * 2 + 1][0] = r1; bf[jb * 2 + 1][1] = r3;
                }
            }
            #pragma unroll
            for (int i = 0; i < IT; i++)
                #pragma unroll
                for (int j = 0; j < 4; j++)
                    mma_bf16(acc[i][j], a[i], bf[j]);
        }

        if (it + 2 < NIT) stage((it + 2) % 3, (it + 2) << 6);
        cp_commit();
    }

    #pragma unroll
    for (int i = 0; i < IT; i++) {
        int r0 = m0 + mbase + i * 16 + (lane >> 2);
        #pragma unroll
        for (int j = 0; j < 4; j++) {
            int c0 = n0 + nbase + j * 8 + (lane & 3) * 2;
            float b0 = 0.f, b1 = 0.f;
            if (bias) { b0 = bias[c0]; b1 = bias[c0 + 1]; }
            float v00 = acc[i][j][0] + b0, v01 = acc[i][j][1] + b1;
            float v10 = acc[i][j][2] + b0, v11 = acc[i][j][3] + b1;
            if (RELU) {
                v00 = fmaxf(v00, 0.f); v01 = fmaxf(v01, 0.f);
                v10 = fmaxf(v10, 0.f); v11 = fmaxf(v11, 0.f);
            }
            if (RES) {
                v00 += res[(long)r0 * ldc + c0];
                v01 += res[(long)r0 * ldc + c0 + 1];
                v10 += res[(long)(r0 + 8) * ldc + c0];
                v11 += res[(long)(r0 + 8) * ldc + c0 + 1];
            }
            if (OUTBF) {
                *(__nv_bfloat162*)(Cb + cbase + (long)r0 * ldc + c0) =
                    __floats2bfloat162_rn(v00, v01);
                *(__nv_bfloat162*)(Cb + cbase + (long)(r0 + 8) * ldc + c0) =
                    __floats2bfloat162_rn(v10, v11);
            } else {
                *(float2*)(Cf + cbase + (long)r0 * ldc + c0)       = make_float2(v00, v01);
                *(float2*)(Cf + cbase + (long)(r0 + 8) * ldc + c0) = make_float2(v10, v11);
            }
        }
    }
}

// ---------------------------------------------------------------------------
extern "C" void kernel_launch(void* const* d_in, const int* in_sizes, int n_in,
                              void* d_out, int out_size)
{
    const float* data    = (const float*)d_in[0];
    const int*   attn_m  = (const int*)  d_in[1];
    const int*   view    = (const int*)  d_in[2];
    const float* seg_emb = (const float*)d_in[3];
    const float* Wq = (const float*)d_in[4];
    const float* bq = (const float*)d_in[5];
    const float* Wk = (const float*)d_in[6];
    const float* bk = (const float*)d_in[7];
    const float* Wv = (const float*)d_in[8];
    const float* bv = (const float*)d_in[9];
    const float* Wo = (const float*)d_in[10];
    const float* bo = (const float*)d_in[11];
    const float* W1 = (const float*)d_in[12];
    const float* b1 = (const float*)d_in[13];
    const float* W2 = (const float*)d_in[14];
    const float* b2 = (const float*)d_in[15];
    const float* alpha1 = (const float*)d_in[16];
    const float* bias1  = (const float*)d_in[17];
    const float* alpha2 = (const float*)d_in[18];
    const float* bias2  = (const float*)d_in[19];
    const float* alpha_f = (const float*)d_in[20];
    const float* bias_f  = (const float*)d_in[21];
    float* out = (float*)d_out;

    float *x;
    __nv_bfloat16 *x2b, *qkv, *ob, *fb;
    __nv_bfloat16 *wqkv, *wo, *w1, *w2;
    float *bqkv;
    cudaGetSymbolAddress((void**)&x,    g_x);
    cudaGetSymbolAddress((void**)&x2b,  g_x2b);
    cudaGetSymbolAddress((void**)&qkv,  g_qkv);
    cudaGetSymbolAddress((void**)&ob,   g_ob);
    cudaGetSymbolAddress((void**)&fb,   g_fb);
    cudaGetSymbolAddress((void**)&wqkv, g_wqkv);
    cudaGetSymbolAddress((void**)&bqkv, g_bqkv);
    cudaGetSymbolAddress((void**)&wo,   g_wo);
    cudaGetSymbolAddress((void**)&w1,   g_w1);
    cudaGetSymbolAddress((void**)&w2,   g_w2);

    constexpr int SM_NN64 = SmemCfg<64,false>::BYTES;     // 79872
    cudaFuncSetAttribute(gemm_bf<64,false,false,true,false>,
        cudaFuncAttributeMaxDynamicSharedMemorySize, SM_NN64);
    cudaFuncSetAttribute(gemm_bf256<false>,
        cudaFuncAttributeMaxDynamicSharedMemorySize, G256_SMEM);
    cudaFuncSetAttribute(gemm_bf256<true>,
        cudaFuncAttributeMaxDynamicSharedMemorySize, G256_SMEM);
    cudaFuncSetAttribute(attn_fused,
        cudaFuncAttributeMaxDynamicSharedMemorySize, ATT_SMEM_BYTES);

    cvt_weights<<<(6 * (WSZ / 4)) / 256, 256>>>(Wq, Wk, Wv, Wo, W1, W2);
    cvt_bias<<<(LNUM * QKVN + 255) / 256, 256>>>(bq, bk, bv);
    embed_kernel<<<(TOK * DMODEL + 255) / 256, 256>>>(data, seg_emb, view, x);

    for (int i = 0; i < LNUM; i++) {
        layernorm_kernel<true><<<TOK / 16, 256>>>(x, alpha1 + i * DMODEL, bias1 + i * DMODEL,
                                                  nullptr, x2b);

        // fused QKV (128x256 tiles): [2048,512] @ [512,6144]
        gemm_bf256<false><<<dim3(QKVN / 256, TOK / 128), 256, G256_SMEM>>>(
            x2b, wqkv + (long)i * DMODEL * QKVN, bqkv + (long)i * QKVN,
            qkv, DMODEL, DMODEL, QKVN, QKVN);

        // fused attention: scores + softmax + PV -> g_ob
        dim3 gs(SS / 128, BB * HEADS);
        attn_fused<<<gs, 256, ATT_SMEM_BYTES>>>(qkv, attn_m, ob);

        // x = x + o @ Wo + bo  (BM=64)
        dim3 go(DMODEL / 128, TOK / 64, 1);
        gemm_bf<64,false,false,true,false><<<go, 256, SM_NN64>>>(
            ob, wo + (long)i * HD * DMODEL, bo + (long)i * DMODEL,
            x, x, nullptr, HD, HD, DMODEL, DMODEL, 0,0,0,0,0,0);

        layernorm_kernel<true><<<TOK / 16, 256>>>(x, alpha2 + i * DMODEL, bias2 + i * DMODEL,
                                                  nullptr, x2b);

        // ff = relu(x2 @ W1 + b1)  (128x256 tiles)
        gemm_bf256<true><<<dim3(DFFN / 256, TOK / 128), 256, G256_SMEM>>>(
            x2b, w1 + (long)i * DMODEL * DFFN, b1 + (long)i * DFFN,
            fb, DMODEL, DMODEL, DFFN, DFFN);

        // x = x + ff @ W2 + b2  (BM=64)
        gemm_bf<64,false,false,true,false><<<go, 256, SM_NN64>>>(
            fb, w2 + (long)i * DFFN * DMODEL, b2 + (long)i * DMODEL,
            x, x, nullptr, DFFN, DFFN, DMODEL, DMODEL, 0,0,0,0,0,0);
    }

    layernorm_kernel<false><<<TOK / 16, 256>>>(x, alpha_f, bias_f, out, nullptr);
}

// round 15
// speedup vs baseline: 1.0225x; 1.0225x over previous
#include <cuda_runtime.h>
#include <cuda_bf16.h>
#include <math.h>
#include <stdint.h>

#define LNUM 4
#define DMODEL 512
#define HEADS 8
#define DKH 256
#define DFFN 2048
#define BB 8
#define SS 256
#define HD (HEADS*DKH)          // 2048
#define TOK (BB*SS)             // 2048
#define QKVN (3*HD)             // 6144
#define EPS 1e-6f

// ---------------- scratch (device globals; no allocations) ----------------
__device__ float g_x [TOK*DMODEL];          // fp32 residual stream

__device__ __nv_bfloat16 g_x2b [TOK*DMODEL];
__device__ __nv_bfloat16 g_qkv [TOK*QKVN];  // packed q|k|v
__device__ __nv_bfloat16 g_ob  [TOK*HD];
__device__ __nv_bfloat16 g_fb  [TOK*DFFN];
// bf16 weights
#define WSZ 4194304                          // 4*512*2048
__device__ __nv_bfloat16 g_wqkv[LNUM*DMODEL*QKVN];   // packed per-layer [512][6144]
__device__ float         g_bqkv[LNUM*QKVN];
__device__ __nv_bfloat16 g_wo[WSZ];
__device__ __nv_bfloat16 g_w1[WSZ];
__device__ __nv_bfloat16 g_w2[WSZ];

// ---------------- PTX helpers ---------------------------------------------
__device__ __forceinline__ void cpa16(uint32_t dst, const void* src) {
    asm volatile("cp.async.cg.shared.global [%0], [%1], 16;" :: "r"(dst), "l"(src) : "memory");
}
__device__ __forceinline__ void cp_commit() {
    asm volatile("cp.async.commit_group;" ::: "memory");
}
template<int N>
__device__ __forceinline__ void cp_wait() {
    asm volatile("cp.async.wait_group %0;" :: "n"(N) : "memory");
}
__device__ __forceinline__ void ldsm4(uint32_t& r0, uint32_t& r1, uint32_t& r2, uint32_t& r3, uint32_t a) {
    asm volatile("ldmatrix.sync.aligned.m8n8.x4.shared.b16 {%0,%1,%2,%3}, [%4];"
                 : "=r"(r0), "=r"(r1), "=r"(r2), "=r"(r3) : "r"(a));
}
__device__ __forceinline__ void ldsm4t(uint32_t& r0, uint32_t& r1, uint32_t& r2, uint32_t& r3, uint32_t a) {
    asm volatile("ldmatrix.sync.aligned.m8n8.x4.trans.shared.b16 {%0,%1,%2,%3}, [%4];"
                 : "=r"(r0), "=r"(r1), "=r"(r2), "=r"(r3) : "r"(a));
}
__device__ __forceinline__ void mma_bf16(float* d, const uint32_t* a, const uint32_t* b) {
    asm volatile("mma.sync.aligned.m16n8k16.row.col.f32.bf16.bf16.f32 "
                 "{%0,%1,%2,%3}, {%4,%5,%6,%7}, {%8,%9}, {%0,%1,%2,%3};"
                 : "+f"(d[0]), "+f"(d[1]), "+f"(d[2]), "+f"(d[3])
                 : "r"(a[0]), "r"(a[1]), "r"(a[2]), "r"(a[3]), "r"(b[0]), "r"(b[1]));
}

// ---------------- weight fp32 -> bf16 (once per launch) -------------------
__global__ void cvt_weights(const float* __restrict__ wq, const float* __restrict__ wk,
                            const float* __restrict__ wv, const float* __restrict__ wo,
                            const float* __restrict__ w1, const float* __restrict__ w2)
{
    long i4 = (long)blockIdx.x * blockDim.x + threadIdx.x;
    int which = (int)(i4 >> 20);
    long off = (i4 & ((1L << 20) - 1)) << 2;
    const float* s;
    __nv_bfloat16* d;
    long doff = off;
    if (which < 3) {
        s = (which == 0) ? wq : (which == 1) ? wk : wv;
        long l   = off / ((long)DMODEL * HD);
        long win = off - l * (long)DMODEL * HD;
        long row = win / HD;
        long col = win - row * HD;
        d = g_wqkv;
        doff = l * (long)DMODEL * QKVN + row * QKVN + which * HD + col;
    } else {
        s = (which == 3) ? wo : (which == 4) ? w1 : w2;
        d = (which == 3) ? g_wo : (which == 4) ? g_w1 : g_w2;
    }
    float4 v = *(const float4*)(s + off);
    *(__nv_bfloat162*)(d + doff)     = __floats2bfloat162_rn(v.x, v.y);
    *(__nv_bfloat162*)(d + doff + 2) = __floats2bfloat162_rn(v.z, v.w);
}

__global__ void cvt_bias(const float* __restrict__ bq, const float* __restrict__ bk,
                         const float* __restrict__ bv)
{
    int idx = blockIdx.x * blockDim.x + threadIdx.x;
    if (idx >= LNUM * QKVN) return;
    int l = idx / QKVN;
    int c = idx - l * QKVN;
    int which = c >> 11;
    int col = c & (HD - 1);
    const float* s = (which == 0) ? bq : (which == 1) ? bk : bv;
    g_bqkv[idx] = s[l * HD + col];
}

// ---------------- embed ----------------------------------------------------
__global__ void embed_kernel(const float* __restrict__ data,
                             const float* __restrict__ seg_emb,
                             const int* __restrict__ view,
                             float* __restrict__ x)
{
    int idx = blockIdx.x * blockDim.x + threadIdx.x;
    if (idx >= TOK * DMODEL) return;
    int c = idx & (DMODEL - 1);
    int s = (idx >> 9) & (SS - 1);
    float inv = exp2f(-(float)c * (1.0f / 32.0f));
    float arg = (float)s * inv;
    float pe  = (c & 1) ? cosf(arg) : sinf(arg);
    int seg_off = view[0] * SS * DMODEL + c;
    x[idx] = data[idx] * sqrtf((float)DMODEL) + pe + seg_emb[seg_off];
}

// ---------------- layernorm: warp handles 2 rows ---------------------------
template<bool OB>
__global__ void layernorm_kernel(const float* __restrict__ x,
                                 const float* __restrict__ alpha,
                                 const float* __restrict__ beta,
                                 float* __restrict__ outf,
                                 __nv_bfloat16* __restrict__ outb)
{
    const int wid = threadIdx.x >> 5, lane = threadIdx.x & 31;
    const int row0 = blockIdx.x * 16 + wid * 2;

    float4 v[2][4];
    float s[2] = {0.f, 0.f}, sq[2] = {0.f, 0.f};
    #pragma unroll
    for (int r = 0; r < 2; r++) {
        const float4* p4 = (const float4*)(x + (long)(row0 + r) * DMODEL);
        #pragma unroll
        for (int j = 0; j < 4; j++) {
            v[r][j] = p4[lane + j * 32];
            s[r]  += v[r][j].x + v[r][j].y + v[r][j].z + v[r][j].w;
            sq[r] += v[r][j].x * v[r][j].x + v[r][j].y * v[r][j].y
                   + v[r][j].z * v[r][j].z + v[r][j].w * v[r][j].w;
        }
    }
    #pragma unroll
    for (int off = 16; off > 0; off >>= 1) {
        s[0]  += __shfl_xor_sync(0xffffffff, s[0],  off);
        sq[0] += __shfl_xor_sync(0xffffffff, sq[0], off);
        s[1]  += __shfl_xor_sync(0xffffffff, s[1],  off);
        sq[1] += __shfl_xor_sync(0xffffffff, sq[1], off);
    }

    const float4* a4 = (const float4*)alpha;
    const float4* b4 = (const float4*)beta;
    #pragma unroll
    for (int r = 0; r < 2; r++) {
        float mean = s[r] * (1.0f / DMODEL);
        float var  = (sq[r] - (float)DMODEL * mean * mean) * (1.0f / (DMODEL - 1));
        var = fmaxf(var, 0.f);
        float rinv = 1.0f / (sqrtf(var) + EPS);
        #pragma unroll
        for (int j = 0; j < 4; j++) {
            float4 av = a4[lane + j * 32];
            float4 bv = b4[lane + j * 32];
            float ox = av.x * (v[r][j].x - mean) * rinv + bv.x;
            float oy = av.y * (v[r][j].y - mean) * rinv + bv.y;
            float oz = av.z * (v[r][j].z - mean) * rinv + bv.z;
            float ow = av.w * (v[r][j].w - mean) * rinv + bv.w;
            long e = (long)(row0 + r) * DMODEL + (lane + j * 32) * 4;
            if (OB) {
                *(__nv_bfloat162*)(outb + e)     = __floats2bfloat162_rn(ox, oy);
                *(__nv_bfloat162*)(outb + e + 2) = __floats2bfloat162_rn(oz, ow);
            } else {
                *(float4*)(outf + e) = make_float4(ox, oy, oz, ow);
            }
        }
    }
}

// ---------------- fused attention: QK^T + mask + softmax + PV -------------
#define ATT_NST 4
#define ATT_SMEM_BYTES 139264
#define ATT_P_ELOFF    0
#define ATT_V_ELOFF    33792
#define ATT_PMAX_BOFF  135168
#define ATT_PSUM_BOFF  137216

__global__ void __launch_bounds__(256)
attn_fused(const __nv_bfloat16* __restrict__ qkv,
           const int* __restrict__ attn_m,
           __nv_bfloat16* __restrict__ ob)
{
    extern __shared__ __align__(16) char smem_raw[];
    __nv_bfloat16* As = (__nv_bfloat16*)smem_raw;
    __nv_bfloat16* Bs = As + ATT_NST * 128 * 40;
    __nv_bfloat16* Ps = (__nv_bfloat16*)smem_raw + ATT_P_ELOFF;
    __nv_bfloat16* Vs = (__nv_bfloat16*)smem_raw + ATT_V_ELOFF;
    float* pmax = (float*)(smem_raw + ATT_PMAX_BOFF);
    float* psum = (float*)(smem_raw + ATT_PSUM_BOFF);
    __shared__ int msk[SS];

    const int z = blockIdx.y;
    const int b = z >> 3, h = z & 7;
    const int m0 = blockIdx.x << 7;
    const long sQb = (long)SS * QKVN;
    const __nv_bfloat16* A = qkv + b * sQb + (long)h * DKH + (long)m0 * QKVN;
    const __nv_bfloat16* K = qkv + HD + b * sQb + (long)h * DKH;
    const __nv_bfloat16* V = qkv + 2 * HD + b * sQb + (long)h * DKH;

    const int tid  = threadIdx.x;
    const int wid  = tid >> 5;
    const int lane = tid & 31;
    const int mbase = (wid >> 2) * 64;
    const int nbase = (wid & 3) * 64;
    const int wn = wid & 3;
    const int lr  = ((lane >> 3) & 1) * 8 + (lane & 7);
    const int lc8 = (lane >> 4) * 8;
    const int lg = lane >> 2, lt = lane & 3;

    if (tid < SS) msk[tid] = attn_m[b * SS + tid];

    uint32_t sAs = (uint32_t)__cvta_generic_to_shared(As);
    uint32_t sBs = (uint32_t)__cvta_generic_to_shared(Bs);
    uint32_t sPs = (uint32_t)__cvta_generic_to_shared(Ps);
    uint32_t sVs = (uint32_t)__cvta_generic_to_shared(Vs);

    float acc[4][8][4];
    #pragma unroll
    for (int i = 0; i < 4; i++)
        #pragma unroll
        for (int j = 0; j < 8; j++)
            #pragma unroll
            for (int r = 0; r < 4; r++) acc[i][j][r] = 0.f;

    auto stageQK = [&](int s, int kb) {
        #pragma unroll
        for (int t = 0; t < 2; t++) {
            int idx = tid + t * 256;
            int row = idx >> 2, ck = idx & 3;
            uint32_t d = sAs + 2u * ((s * 128 + row) * 40 + ck * 8);
            cpa16(d, A + (long)row * QKVN + kb + ck * 8);
        }
        #pragma unroll
        for (int t = 0; t < 4; t++) {
            int idx = tid + t * 256;
            int row = idx >> 2, ck = idx & 3;
            uint32_t d = sBs + 2u * ((s * 256 + row) * 40 + ck * 8);
            cpa16(d, K + (long)row * QKVN + kb + ck * 8);
        }
    };

    const int NIT = DKH / 32;     // 8
    stageQK(0, 0);  cp_commit();
    stageQK(1, 32); cp_commit();
    stageQK(2, 64); cp_commit();

    for (int it = 0; it < NIT; it++) {
        int s = it & 3;
        cp_wait<2>();
        __syncthreads();

        #pragma unroll
        for (int ks = 0; ks < 32; ks += 16) {
            uint32_t a[4][4], bf[8][2];
            #pragma unroll
            for (int i = 0; i < 4; i++) {
                uint32_t addr = sAs + 2u * ((s * 128 + mbase + i * 16 + lr) * 40 + ks + lc8);
                ldsm4(a[i][0], a[i][1], a[i][2], a[i][3], addr);
            }
            #pragma unroll
            for (int jb = 0; jb < 4; jb++) {
                uint32_t r0, r1, r2, r3;
                uint32_t addr = sBs + 2u * ((s * 256 + nbase + jb * 16 + lr) * 40 + ks + lc8);
                ldsm4(r0, r1, r2, r3, addr);
                bf[jb * 2 + 0][0] = r0; bf[jb * 2 + 0][1] = r2;
                bf[jb * 2 + 1][0] = r1; bf[jb * 2 + 1][1] = r3;
            }
            #pragma unroll
            for (int i = 0; i < 4; i++)
                #pragma unroll
                for (int j = 0; j < 8; j++)
                    mma_bf16(acc[i][j], a[i], bf[j]);
        }

        if (it + 3 < NIT) stageQK((it + 3) & 3, (it + 3) << 5);
        cp_commit();
    }
    cp_wait<0>();
    __syncthreads();

    auto stageV = [&](int s, int k0) {
        #pragma unroll
        for (int t = 0; t < 4; t++) {
            int idx = tid + t * 256;
            int row = idx >> 5, c8 = idx & 31;
            uint32_t d = sVs + 2u * ((s * 32 + row) * 264 + c8 * 8);
            cpa16(d, V + (long)(k0 + row) * QKVN + c8 * 8);
        }
    };
    stageV(0, 0);  cp_commit();
    stageV(1, 32); cp_commit();
    stageV(2, 64); cp_commit();

    #pragma unroll
    for (int i = 0; i < 4; i++) {
        float m0v = -1e30f, m1v = -1e30f;
        #pragma unroll
        for (int j = 0; j < 8; j++) {
            int c0 = nbase + j * 8 + lt * 2;
            bool k0 = msk[c0] != 0, k1 = msk[c0 + 1] != 0;
            acc[i][j][0] = k0 ? -1e9f : acc[i][j][0] * 0.0625f;
            acc[i][j][1] = k1 ? -1e9f : acc[i][j][1] * 0.0625f;
            acc[i][j][2] = k0 ? -1e9f : acc[i][j][2] * 0.0625f;
            acc[i][j][3] = k1 ? -1e9f : acc[i][j][3] * 0.0625f;
            m0v = fmaxf(m0v, fmaxf(acc[i][j][0], acc[i][j][1]));
            m1v = fmaxf(m1v, fmaxf(acc[i][j][2], acc[i][j][3]));
        }
        m0v = fmaxf(m0v, __shfl_xor_sync(0xffffffff, m0v, 1));
        m0v = fmaxf(m0v, __shfl_xor_sync(0xffffffff, m0v, 2));
        m1v = fmaxf(m1v, __shfl_xor_sync(0xffffffff, m1v, 1));
        m1v = fmaxf(m1v, __shfl_xor_sync(0xffffffff, m1v, 2));
        if (lt == 0) {
            pmax[(mbase + i * 16 + lg) * 4 + wn]     = m0v;
            pmax[(mbase + i * 16 + 8 + lg) * 4 + wn] = m1v;
        }
    }
    __syncthreads();

    float rinv0[4], rinv1[4];
    #pragma unroll
    for (int i = 0; i < 4; i++) {
        int r0 = mbase + i * 16 + lg;
        const float* px0 = pmax + r0 * 4;
        const float* px1 = pmax + (r0 + 8) * 4;
        float g0 = fmaxf(fmaxf(px0[0], px0[1]), fmaxf(px0[2], px0[3]));
        float g1 = fmaxf(fmaxf(px1[0], px1[1]), fmaxf(px1[2], px1[3]));
        float s0 = 0.f, s1 = 0.f;
        #pragma unroll
        for (int j = 0; j < 8; j++) {
            acc[i][j][0] = expf(acc[i][j][0] - g0);
            acc[i][j][1] = expf(acc[i][j][1] - g0);
            acc[i][j][2] = expf(acc[i][j][2] - g1);
            acc[i][j][3] = expf(acc[i][j][3] - g1);
            s0 += acc[i][j][0] + acc[i][j][1];
            s1 += acc[i][j][2] + acc[i][j][3];
        }
        s0 += __shfl_xor_sync(0xffffffff, s0, 1);
        s0 += __shfl_xor_sync(0xffffffff, s0, 2);
        s1 += __shfl_xor_sync(0xffffffff, s1, 1);
        s1 += __shfl_xor_sync(0xffffffff, s1, 2);
        if (lt == 0) {
            psum[r0 * 4 + wn]       = s0;
            psum[(r0 + 8) * 4 + wn] = s1;
        }
    }
    __syncthreads();

    #pragma unroll
    for (int i = 0; i < 4; i++) {
        int r0 = mbase + i * 16 + lg;
        const float* ps0 = psum + r0 * 4;
        const float* ps1 = psum + (r0 + 8) * 4;
        rinv0[i] = 1.0f / (ps0[0] + ps0[1] + ps0[2] + ps0[3]);
        rinv1[i] = 1.0f / (ps1[0] + ps1[1] + ps1[2] + ps1[3]);
        #pragma unroll
        for (int j = 0; j < 8; j++) {
            int c0 = nbase + j * 8 + lt * 2;
            *(__nv_bfloat162*)(Ps + (r0 * 264 + c0)) =
                __floats2bfloat162_rn(acc[i][j][0] * rinv0[i], acc[i][j][1] * rinv0[i]);
            *(__nv_bfloat162*)(Ps + ((r0 + 8) * 264 + c0)) =
                __floats2bfloat162_rn(acc[i][j][2] * rinv1[i], acc[i][j][3] * rinv1[i]);
        }
    }

    #pragma unroll
    for (int i = 0; i < 4; i++)
        #pragma unroll
        for (int j = 0; j < 8; j++)
            #pragma unroll
            for (int r = 0; r < 4; r++) acc[i][j][r] = 0.f;

    for (int it = 0; it < 8; it++) {
        int s = it & 3;
        cp_wait<2>();
        __syncthreads();

        #pragma unroll
        for (int ks = 0; ks < 32; ks += 16) {
            int kg = it * 32 + ks;
            uint32_t a[4][4], bf[8][2];
            #pragma unroll
            for (int i = 0; i < 4; i++) {
                uint32_t addr = sPs + 2u * ((mbase + i * 16 + lr) * 264 + kg + lc8);
                ldsm4(a[i][0], a[i][1], a[i][2], a[i][3], addr);
            }
            #pragma unroll
            for (int jb = 0; jb < 4; jb++) {
                uint32_t r0, r1, r2, r3;
                uint32_t addr = sVs + 2u * ((s * 32 + ks + lr) * 264 + nbase + jb * 16 + lc8);
                ldsm4t(r0, r1, r2, r3, addr);
                bf[jb * 2 + 0][0] = r0; bf[jb * 2 + 0][1] = r1;
                bf[jb * 2 + 1][0] = r2; bf[jb * 2 + 1][1] = r3;
            }
            #pragma unroll
            for (int i = 0; i < 4; i++)
                #pragma unroll
                for (int j = 0; j < 8; j++)
                    mma_bf16(acc[i][j], a[i], bf[j]);
        }

        if (it + 3 < 8) stageV((it + 3) & 3, (it + 3) << 5);
        cp_commit();
    }

    #pragma unroll
    for (int i = 0; i < 4; i++) {
        int r0 = mbase + i * 16 + lg;
        long base0 = (long)(b * SS + m0 + r0) * HD + h * DKH;
        long base1 = (long)(b * SS + m0 + r0 + 8) * HD + h * DKH;
        #pragma unroll
        for (int j = 0; j < 8; j++) {
            int c0 = nbase + j * 8 + lt * 2;
            *(__nv_bfloat162*)(ob + base0 + c0) =
                __floats2bfloat162_rn(acc[i][j][0], acc[i][j][1]);
            *(__nv_bfloat162*)(ob + base1 + c0) =
                __floats2bfloat162_rn(acc[i][j][2], acc[i][j][3]);
        }
    }
}

// ---------------- bf16 HMMA GEMM, BK=64, 3-stage cp.async -----------------
#define NSTAGE 3
template<int BM, bool TB>
struct SmemCfg {
    static constexpr int AROW  = 72;
    static constexpr int BROWS = TB ? 128 : 64;
    static constexpr int BCOLS = TB ? 72 : 136;
    static constexpr int A_ELEMS = NSTAGE * BM * AROW;
    static constexpr int B_ELEMS = NSTAGE * BROWS * BCOLS;
    static constexpr int BYTES = (A_ELEMS + B_ELEMS) * 2;
};

template<int BM, bool TB, bool RELU, bool RES, bool OUTBF>
__global__ void __launch_bounds__(256)
gemm_bf(const __nv_bfloat16* __restrict__ A, const __nv_bfloat16* __restrict__ B,
        const float* __restrict__ bias, const float* __restrict__ res,
        float* __restrict__ Cf, __nv_bfloat16* __restrict__ Cb,
        int K, int lda, int ldb, int ldc,
        long sAb, long sAh, long sBb, long sBh, long sCb, long sCh)
{
    constexpr int IT = BM / 32;

    extern __shared__ __align__(16) char smem_raw[];
    __nv_bfloat16* As = (__nv_bfloat16*)smem_raw;
    __nv_bfloat16* Bs = As + SmemCfg<BM,TB>::A_ELEMS;

    int z = blockIdx.z;
    int bb = z >> 3, hh = z & 7;
    A += bb * sAb + hh * sAh;
    B += bb * sBb + hh * sBh;
    if (RES) res += bb * sCb + hh * sCh;
    long cbase = bb * sCb + hh * sCh;

    const int m0 = blockIdx.y * BM, n0 = blockIdx.x << 7;
    const int tid  = threadIdx.x;
    const int wid  = tid >> 5;
    const int lane = tid & 31;
    const int mbase = (wid >> 2) * (BM / 2);
    const int nbase = (wid & 3) * 32;
    const int lr  = ((lane >> 3) & 1) * 8 + (lane & 7);
    const int lc8 = (lane >> 4) * 8;

    uint32_t sAs = (uint32_t)__cvta_generic_to_shared(As);
    uint32_t sBs = (uint32_t)__cvta_generic_to_shared(Bs);

    float acc[IT][4][4];
    #pragma unroll
    for (int i = 0; i < IT; i++)
        #pragma unroll
        for (int j = 0; j < 4; j++)
            #pragma unroll
            for (int r = 0; r < 4; r++) acc[i][j][r] = 0.f;

    auto stage = [&](int s, int kb) {
        #pragma unroll
        for (int t = 0; t < BM / 32; t++) {
            int idx = tid + t * 256;
            int row = idx >> 3, ck = idx & 7;
            uint32_t d = sAs + 2u * ((s * BM + row) * 72 + ck * 8);
            cpa16(d, A + (long)(m0 + row) * lda + kb + ck * 8);
        }
        if (!TB) {
            #pragma unroll
            for (int t = 0; t < 4; t++) {
                int idx = tid + t * 256;
                int row = idx >> 4, ck = idx & 15;
                uint32_t d = sBs + 2u * ((s * 64 + row) * 136 + ck * 8);
                cpa16(d, B + (long)(kb + row) * ldb + n0 + ck * 8);
            }
        } else {
            #pragma unroll
            for (int t = 0; t < 4; t++) {
                int idx = tid + t * 256;
                int row = idx >> 3, ck = idx & 7;
                uint32_t d = sBs + 2u * ((s * 128 + row) * 72 + ck * 8);
                cpa16(d, B + (long)(n0 + row) * ldb + kb + ck * 8);
            }
        }
    };

    const int NIT = K >> 6;
    stage(0, 0);  cp_commit();
    stage(1, 64); cp_commit();

    for (int it = 0; it < NIT; it++) {
        int s = it % 3;
        cp_wait<1>();
        __syncthreads();

        #pragma unroll
        for (int ks = 0; ks < 64; ks += 16) {
            uint32_t a[IT][4], bf[4][2];
            #pragma unroll
            for (int i = 0; i < IT; i++) {
                uint32_t addr = sAs + 2u * ((s * BM + mbase + i * 16 + lr) * 72 + ks + lc8);
                ldsm4(a[i][0], a[i][1], a[i][2], a[i][3], addr);
            }
            #pragma unroll
            for (int jb = 0; jb < 2; jb++) {
                uint32_t r0, r1, r2, r3;
                if (!TB) {
                    uint32_t addr = sBs + 2u * ((s * 64 + ks + lr) * 136 + nbase + jb * 16 + lc8);
                    ldsm4t(r0, r1, r2, r3, addr);
                    bf[jb * 2 + 0][0] = r0; bf[jb * 2 + 0][1] = r1;
                    bf[jb * 2 + 1][0] = r2; bf[jb * 2 + 1][1] = r3;
                } else {
                    uint32_t addr = sBs + 2u * ((s * 128 + nbase + jb * 16 + lr) * 72 + ks + lc8);
                    ldsm4(r0, r1, r2, r3, addr);
                    bf[jb * 2 + 0][0] = r0; bf[jb * 2 + 0][1] = r2;
                    bf[jb * 2 + 1][0] = r1; bf[jb * 2 + 1][1] = r3;
                }
            }
            #pragma unroll
            for (int i = 0; i < IT; i++)
                #pragma unroll
                for (int j = 0; j < 4; j++)
                    mma_bf16(acc[i][j], a[i], bf[j]);
        }

        if (it + 2 < NIT) stage((it + 2) % 3, (it + 2) << 6);
        cp_commit();
    }

    #pragma unroll
    for (int i = 0; i < IT; i++) {
        int r0 = m0 + mbase + i * 16 + (lane >> 2);
        #pragma unroll
        for (int j = 0; j < 4; j++) {
            int c0 = n0 + nbase + j * 8 + (lane & 3) * 2;
            float b0 = 0.f, b1 = 0.f;
            if (bias) { b0 = bias[c0]; b1 = bias[c0 + 1]; }
            float v00 = acc[i][j][0] + b0, v01 = acc[i][j][1] + b1;
            float v10 = acc[i][j][2] + b0, v11 = acc[i][j][3] + b1;
            if (RELU) {
                v00 = fmaxf(v00, 0.f); v01 = fmaxf(v01, 0.f);
                v10 = fmaxf(v10, 0.f); v11 = fmaxf(v11, 0.f);
            }
            if (RES) {
                v00 += res[(long)r0 * ldc + c0];
                v01 += res[(long)r0 * ldc + c0 + 1];
                v10 += res[(long)(r0 + 8) * ldc + c0];
                v11 += res[(long)(r0 + 8) * ldc + c0 + 1];
            }
            if (OUTBF) {
                *(__nv_bfloat162*)(Cb + cbase + (long)r0 * ldc + c0) =
                    __floats2bfloat162_rn(v00, v01);
                *(__nv_bfloat162*)(Cb + cbase + (long)(r0 + 8) * ldc + c0) =
                    __floats2bfloat162_rn(v10, v11);
            } else {
                *(float2*)(Cf + cbase + (long)r0 * ldc + c0)       = make_float2(v00, v01);
                *(float2*)(Cf + cbase + (long)(r0 + 8) * ldc + c0) = make_float2(v10, v11);
            }
        }
    }
}

// ---------------------------------------------------------------------------
extern "C" void kernel_launch(void* const* d_in, const int* in_sizes, int n_in,
                              void* d_out, int out_size)
{
    const float* data    = (const float*)d_in[0];
    const int*   attn_m  = (const int*)  d_in[1];
    const int*   view    = (const int*)  d_in[2];
    const float* seg_emb = (const float*)d_in[3];
    const float* Wq = (const float*)d_in[4];
    const float* bq = (const float*)d_in[5];
    const float* Wk = (const float*)d_in[6];
    const float* bk = (const float*)d_in[7];
    const float* Wv = (const float*)d_in[8];
    const float* bv = (const float*)d_in[9];
    const float* Wo = (const float*)d_in[10];
    const float* bo = (const float*)d_in[11];
    const float* W1 = (const float*)d_in[12];
    const float* b1 = (const float*)d_in[13];
    const float* W2 = (const float*)d_in[14];
    const float* b2 = (const float*)d_in[15];
    const float* alpha1 = (const float*)d_in[16];
    const float* bias1  = (const float*)d_in[17];
    const float* alpha2 = (const float*)d_in[18];
    const float* bias2  = (const float*)d_in[19];
    const float* alpha_f = (const float*)d_in[20];
    const float* bias_f  = (const float*)d_in[21];
    float* out = (float*)d_out;

    float *x;
    __nv_bfloat16 *x2b, *qkv, *ob, *fb;
    __nv_bfloat16 *wqkv, *wo, *w1, *w2;
    float *bqkv;
    cudaGetSymbolAddress((void**)&x,    g_x);
    cudaGetSymbolAddress((void**)&x2b,  g_x2b);
    cudaGetSymbolAddress((void**)&qkv,  g_qkv);
    cudaGetSymbolAddress((void**)&ob,   g_ob);
    cudaGetSymbolAddress((void**)&fb,   g_fb);
    cudaGetSymbolAddress((void**)&wqkv, g_wqkv);
    cudaGetSymbolAddress((void**)&bqkv, g_bqkv);
    cudaGetSymbolAddress((void**)&wo,   g_wo);
    cudaGetSymbolAddress((void**)&w1,   g_w1);
    cudaGetSymbolAddress((void**)&w2,   g_w2);

    constexpr int SM_NN128 = SmemCfg<128,false>::BYTES;   // 107520
    constexpr int SM_NN64  = SmemCfg<64, false>::BYTES;   // 79872
    cudaFuncSetAttribute(gemm_bf<128,false,false,false,true>,
        cudaFuncAttributeMaxDynamicSharedMemorySize, SM_NN128);
    cudaFuncSetAttribute(gemm_bf<128,false,true,false,true>,
        cudaFuncAttributeMaxDynamicSharedMemorySize, SM_NN128);
    cudaFuncSetAttribute(gemm_bf<64,false,false,true,false>,
        cudaFuncAttributeMaxDynamicSharedMemorySize, SM_NN64);
    cudaFuncSetAttribute(attn_fused,
        cudaFuncAttributeMaxDynamicSharedMemorySize, ATT_SMEM_BYTES);

    cvt_weights<<<(6 * (WSZ / 4)) / 256, 256>>>(Wq, Wk, Wv, Wo, W1, W2);
    cvt_bias<<<(LNUM * QKVN + 255) / 256, 256>>>(bq, bk, bv);
    embed_kernel<<<(TOK * DMODEL + 255) / 256, 256>>>(data, seg_emb, view, x);

    for (int i = 0; i < LNUM; i++) {
        layernorm_kernel<true><<<TOK / 16, 256>>>(x, alpha1 + i * DMODEL, bias1 + i * DMODEL,
                                                  nullptr, x2b);

        // fused QKV: [2048,512] @ [512,6144]
        dim3 gp(QKVN / 128, TOK / 128, 1);
        gemm_bf<128,false,false,false,true><<<gp, 256, SM_NN128>>>(
            x2b, wqkv + (long)i * DMODEL * QKVN, bqkv + (long)i * QKVN,
            nullptr, nullptr, qkv, DMODEL, DMODEL, QKVN, QKVN, 0,0,0,0,0,0);

        // fused attention: scores + softmax + PV -> g_ob
        dim3 gs(SS / 128, BB * HEADS);
        attn_fused<<<gs, 256, ATT_SMEM_BYTES>>>(qkv, attn_m, ob);

        // x = x + o @ Wo + bo  (BM=64)
        dim3 go(DMODEL / 128, TOK / 64, 1);
        gemm_bf<64,false,false,true,false><<<go, 256, SM_NN64>>>(
            ob, wo + (long)i * HD * DMODEL, bo + (long)i * DMODEL,
            x, x, nullptr, HD, HD, DMODEL, DMODEL, 0,0,0,0,0,0);

        layernorm_kernel<true><<<TOK / 16, 256>>>(x, alpha2 + i * DMODEL, bias2 + i * DMODEL,
                                                  nullptr, x2b);

        // ff = relu(x2 @ W1 + b1)
        dim3 gf(DFFN / 128, TOK / 128, 1);
        gemm_bf<128,false,true,false,true><<<gf, 256, SM_NN128>>>(
            x2b, w1 + (long)i * DMODEL * DFFN, b1 + (long)i * DFFN,
            nullptr, nullptr, fb, DMODEL, DMODEL, DFFN, DFFN, 0,0,0,0,0,0);

        // x = x + ff @ W2 + b2  (BM=64)
        gemm_bf<64,false,false,true,false><<<go, 256, SM_NN64>>>(
            fb, w2 + (long)i * DFFN * DMODEL, b2 + (long)i * DMODEL,
            x, x, nullptr, DFFN, DFFN, DMODEL, DMODEL, 0,0,0,0,0,0);
    }

    layernorm_kernel<false><<<TOK / 16, 256>>>(x, alpha_f, bias_f, out, nullptr);
}

// round 16
// speedup vs baseline: 1.0294x; 1.0068x over previous
#include <cuda_runtime.h>
#include <cuda_bf16.h>
#include <math.h>
#include <stdint.h>

#define LNUM 4
#define DMODEL 512
#define HEADS 8
#define DKH 256
#define DFFN 2048
#define BB 8
#define SS 256
#define HD (HEADS*DKH)          // 2048
#define TOK (BB*SS)             // 2048
#define QKVN (3*HD)             // 6144
#define EPS 1e-6f

// ---------------- scratch (device globals; no allocations) ----------------
__device__ float g_x [TOK*DMODEL];          // fp32 residual stream

__device__ __nv_bfloat16 g_x2b [TOK*DMODEL];
__device__ __nv_bfloat16 g_qkv [TOK*QKVN];  // packed q|k|v
__device__ __nv_bfloat16 g_ob  [TOK*HD];
__device__ __nv_bfloat16 g_fb  [TOK*DFFN];
// bf16 weights
#define WSZ 4194304                          // 4*512*2048
__device__ __nv_bfloat16 g_wqkv[LNUM*DMODEL*QKVN];   // packed per-layer [512][6144]
__device__ float         g_bqkv[LNUM*QKVN];
__device__ __nv_bfloat16 g_wo[WSZ];
__device__ __nv_bfloat16 g_w1[WSZ];
__device__ __nv_bfloat16 g_w2[WSZ];

// ---------------- PTX helpers ---------------------------------------------
__device__ __forceinline__ void cpa16(uint32_t dst, const void* src) {
    asm volatile("cp.async.cg.shared.global [%0], [%1], 16;" :: "r"(dst), "l"(src) : "memory");
}
__device__ __forceinline__ void cp_commit() {
    asm volatile("cp.async.commit_group;" ::: "memory");
}
template<int N>
__device__ __forceinline__ void cp_wait() {
    asm volatile("cp.async.wait_group %0;" :: "n"(N) : "memory");
}
__device__ __forceinline__ void ldsm4(uint32_t& r0, uint32_t& r1, uint32_t& r2, uint32_t& r3, uint32_t a) {
    asm volatile("ldmatrix.sync.aligned.m8n8.x4.shared.b16 {%0,%1,%2,%3}, [%4];"
                 : "=r"(r0), "=r"(r1), "=r"(r2), "=r"(r3) : "r"(a));
}
__device__ __forceinline__ void ldsm4t(uint32_t& r0, uint32_t& r1, uint32_t& r2, uint32_t& r3, uint32_t a) {
    asm volatile("ldmatrix.sync.aligned.m8n8.x4.trans.shared.b16 {%0,%1,%2,%3}, [%4];"
                 : "=r"(r0), "=r"(r1), "=r"(r2), "=r"(r3) : "r"(a));
}
__device__ __forceinline__ void mma_bf16(float* d, const uint32_t* a, const uint32_t* b) {
    asm volatile("mma.sync.aligned.m16n8k16.row.col.f32.bf16.bf16.f32 "
                 "{%0,%1,%2,%3}, {%4,%5,%6,%7}, {%8,%9}, {%0,%1,%2,%3};"
                 : "+f"(d[0]), "+f"(d[1]), "+f"(d[2]), "+f"(d[3])
                 : "r"(a[0]), "r"(a[1]), "r"(a[2]), "r"(a[3]), "r"(b[0]), "r"(b[1]));
}

// ---------------- weight fp32 -> bf16 (once per launch) -------------------
__global__ void cvt_weights(const float* __restrict__ wq, const float* __restrict__ wk,
                            const float* __restrict__ wv, const float* __restrict__ wo,
                            const float* __restrict__ w1, const float* __restrict__ w2)
{
    long i4 = (long)blockIdx.x * blockDim.x + threadIdx.x;
    int which = (int)(i4 >> 20);
    long off = (i4 & ((1L << 20) - 1)) << 2;
    const float* s;
    __nv_bfloat16* d;
    long doff = off;
    if (which < 3) {
        s = (which == 0) ? wq : (which == 1) ? wk : wv;
        long l   = off / ((long)DMODEL * HD);
        long win = off - l * (long)DMODEL * HD;
        long row = win / HD;
        long col = win - row * HD;
        d = g_wqkv;
        doff = l * (long)DMODEL * QKVN + row * QKVN + which * HD + col;
    } else {
        s = (which == 3) ? wo : (which == 4) ? w1 : w2;
        d = (which == 3) ? g_wo : (which == 4) ? g_w1 : g_w2;
    }
    float4 v = *(const float4*)(s + off);
    *(__nv_bfloat162*)(d + doff)     = __floats2bfloat162_rn(v.x, v.y);
    *(__nv_bfloat162*)(d + doff + 2) = __floats2bfloat162_rn(v.z, v.w);
}

__global__ void cvt_bias(const float* __restrict__ bq, const float* __restrict__ bk,
                         const float* __restrict__ bv)
{
    int idx = blockIdx.x * blockDim.x + threadIdx.x;
    if (idx >= LNUM * QKVN) return;
    int l = idx / QKVN;
    int c = idx - l * QKVN;
    int which = c >> 11;
    int col = c & (HD - 1);
    const float* s = (which == 0) ? bq : (which == 1) ? bk : bv;
    g_bqkv[idx] = s[l * HD + col];
}

// ---------------- embed ----------------------------------------------------
__global__ void embed_kernel(const float* __restrict__ data,
                             const float* __restrict__ seg_emb,
                             const int* __restrict__ view,
                             float* __restrict__ x)
{
    int idx = blockIdx.x * blockDim.x + threadIdx.x;
    if (idx >= TOK * DMODEL) return;
    int c = idx & (DMODEL - 1);
    int s = (idx >> 9) & (SS - 1);
    float inv = exp2f(-(float)c * (1.0f / 32.0f));
    float arg = (float)s * inv;
    float pe  = (c & 1) ? cosf(arg) : sinf(arg);
    int seg_off = view[0] * SS * DMODEL + c;
    x[idx] = data[idx] * sqrtf((float)DMODEL) + pe + seg_emb[seg_off];
}

// ---------------- layernorm: warp handles 2 rows ---------------------------
template<bool OB>
__global__ void layernorm_kernel(const float* __restrict__ x,
                                 const float* __restrict__ alpha,
                                 const float* __restrict__ beta,
                                 float* __restrict__ outf,
                                 __nv_bfloat16* __restrict__ outb)
{
    const int wid = threadIdx.x >> 5, lane = threadIdx.x & 31;
    const int row0 = blockIdx.x * 16 + wid * 2;

    float4 v[2][4];
    float s[2] = {0.f, 0.f}, sq[2] = {0.f, 0.f};
    #pragma unroll
    for (int r = 0; r < 2; r++) {
        const float4* p4 = (const float4*)(x + (long)(row0 + r) * DMODEL);
        #pragma unroll
        for (int j = 0; j < 4; j++) {
            v[r][j] = p4[lane + j * 32];
            s[r]  += v[r][j].x + v[r][j].y + v[r][j].z + v[r][j].w;
            sq[r] += v[r][j].x * v[r][j].x + v[r][j].y * v[r][j].y
                   + v[r][j].z * v[r][j].z + v[r][j].w * v[r][j].w;
        }
    }
    #pragma unroll
    for (int off = 16; off > 0; off >>= 1) {
        s[0]  += __shfl_xor_sync(0xffffffff, s[0],  off);
        sq[0] += __shfl_xor_sync(0xffffffff, sq[0], off);
        s[1]  += __shfl_xor_sync(0xffffffff, s[1],  off);
        sq[1] += __shfl_xor_sync(0xffffffff, sq[1], off);
    }

    const float4* a4 = (const float4*)alpha;
    const float4* b4 = (const float4*)beta;
    #pragma unroll
    for (int r = 0; r < 2; r++) {
        float mean = s[r] * (1.0f / DMODEL);
        float var  = (sq[r] - (float)DMODEL * mean * mean) * (1.0f / (DMODEL - 1));
        var = fmaxf(var, 0.f);
        float rinv = 1.0f / (sqrtf(var) + EPS);
        #pragma unroll
        for (int j = 0; j < 4; j++) {
            float4 av = a4[lane + j * 32];
            float4 bv = b4[lane + j * 32];
            float ox = av.x * (v[r][j].x - mean) * rinv + bv.x;
            float oy = av.y * (v[r][j].y - mean) * rinv + bv.y;
            float oz = av.z * (v[r][j].z - mean) * rinv + bv.z;
            float ow = av.w * (v[r][j].w - mean) * rinv + bv.w;
            long e = (long)(row0 + r) * DMODEL + (lane + j * 32) * 4;
            if (OB) {
                *(__nv_bfloat162*)(outb + e)     = __floats2bfloat162_rn(ox, oy);
                *(__nv_bfloat162*)(outb + e + 2) = __floats2bfloat162_rn(oz, ow);
            } else {
                *(float4*)(outf + e) = make_float4(ox, oy, oz, ow);
            }
        }
    }
}

// ---------------- fused attention: QK^T + mask + softmax + PV -------------
#define ATT_NST 4
#define ATT_SMEM_BYTES 139264
#define ATT_P_ELOFF    0
#define ATT_V_ELOFF    33792
#define ATT_PMAX_BOFF  135168
#define ATT_PSUM_BOFF  137216

__global__ void __launch_bounds__(256)
attn_fused(const __nv_bfloat16* __restrict__ qkv,
           const int* __restrict__ attn_m,
           __nv_bfloat16* __restrict__ ob)
{
    extern __shared__ __align__(16) char smem_raw[];
    __nv_bfloat16* As = (__nv_bfloat16*)smem_raw;
    __nv_bfloat16* Bs = As + ATT_NST * 128 * 40;
    __nv_bfloat16* Ps = (__nv_bfloat16*)smem_raw + ATT_P_ELOFF;
    __nv_bfloat16* Vs = (__nv_bfloat16*)smem_raw + ATT_V_ELOFF;
    float* pmax = (float*)(smem_raw + ATT_PMAX_BOFF);
    float* psum = (float*)(smem_raw + ATT_PSUM_BOFF);
    __shared__ int msk[SS];

    const int z = blockIdx.y;
    const int b = z >> 3, h = z & 7;
    const int m0 = blockIdx.x << 7;
    const long sQb = (long)SS * QKVN;
    const __nv_bfloat16* A = qkv + b * sQb + (long)h * DKH + (long)m0 * QKVN;
    const __nv_bfloat16* K = qkv + HD + b * sQb + (long)h * DKH;
    const __nv_bfloat16* V = qkv + 2 * HD + b * sQb + (long)h * DKH;

    const int tid  = threadIdx.x;
    const int wid  = tid >> 5;
    const int lane = tid & 31;
    const int mbase = (wid >> 2) * 64;
    const int nbase = (wid & 3) * 64;
    const int wn = wid & 3;
    const int lr  = ((lane >> 3) & 1) * 8 + (lane & 7);
    const int lc8 = (lane >> 4) * 8;
    const int lg = lane >> 2, lt = lane & 3;

    if (tid < SS) msk[tid] = attn_m[b * SS + tid];

    uint32_t sAs = (uint32_t)__cvta_generic_to_shared(As);
    uint32_t sBs = (uint32_t)__cvta_generic_to_shared(Bs);
    uint32_t sPs = (uint32_t)__cvta_generic_to_shared(Ps);
    uint32_t sVs = (uint32_t)__cvta_generic_to_shared(Vs);

    float acc[4][8][4];
    #pragma unroll
    for (int i = 0; i < 4; i++)
        #pragma unroll
        for (int j = 0; j < 8; j++)
            #pragma unroll
            for (int r = 0; r < 4; r++) acc[i][j][r] = 0.f;

    auto stageQK = [&](int s, int kb) {
        #pragma unroll
        for (int t = 0; t < 2; t++) {
            int idx = tid + t * 256;
            int row = idx >> 2, ck = idx & 3;
            uint32_t d = sAs + 2u * ((s * 128 + row) * 40 + ck * 8);
            cpa16(d, A + (long)row * QKVN + kb + ck * 8);
        }
        #pragma unroll
        for (int t = 0; t < 4; t++) {
            int idx = tid + t * 256;
            int row = idx >> 2, ck = idx & 3;
            uint32_t d = sBs + 2u * ((s * 256 + row) * 40 + ck * 8);
            cpa16(d, K + (long)row * QKVN + kb + ck * 8);
        }
    };

    const int NIT = DKH / 32;     // 8
    stageQK(0, 0);  cp_commit();
    stageQK(1, 32); cp_commit();
    stageQK(2, 64); cp_commit();

    for (int it = 0; it < NIT; it++) {
        int s = it & 3;
        cp_wait<2>();
        __syncthreads();

        #pragma unroll
        for (int ks = 0; ks < 32; ks += 16) {
            uint32_t a[4][4], bf[8][2];
            #pragma unroll
            for (int i = 0; i < 4; i++) {
                uint32_t addr = sAs + 2u * ((s * 128 + mbase + i * 16 + lr) * 40 + ks + lc8);
                ldsm4(a[i][0], a[i][1], a[i][2], a[i][3], addr);
            }
            #pragma unroll
            for (int jb = 0; jb < 4; jb++) {
                uint32_t r0, r1, r2, r3;
                uint32_t addr = sBs + 2u * ((s * 256 + nbase + jb * 16 + lr) * 40 + ks + lc8);
                ldsm4(r0, r1, r2, r3, addr);
                bf[jb * 2 + 0][0] = r0; bf[jb * 2 + 0][1] = r2;
                bf[jb * 2 + 1][0] = r1; bf[jb * 2 + 1][1] = r3;
            }
            #pragma unroll
            for (int i = 0; i < 4; i++)
                #pragma unroll
                for (int j = 0; j < 8; j++)
                    mma_bf16(acc[i][j], a[i], bf[j]);
        }

        if (it + 3 < NIT) stageQK((it + 3) & 3, (it + 3) << 5);
        cp_commit();
    }
    cp_wait<0>();
    __syncthreads();

    auto stageV = [&](int s, int k0) {
        #pragma unroll
        for (int t = 0; t < 4; t++) {
            int idx = tid + t * 256;
            int row = idx >> 5, c8 = idx & 31;
            uint32_t d = sVs + 2u * ((s * 32 + row) * 264 + c8 * 8);
            cpa16(d, V + (long)(k0 + row) * QKVN + c8 * 8);
        }
    };
    stageV(0, 0);  cp_commit();
    stageV(1, 32); cp_commit();
    stageV(2, 64); cp_commit();

    #pragma unroll
    for (int i = 0; i < 4; i++) {
        float m0v = -1e30f, m1v = -1e30f;
        #pragma unroll
        for (int j = 0; j < 8; j++) {
            int c0 = nbase + j * 8 + lt * 2;
            bool k0 = msk[c0] != 0, k1 = msk[c0 + 1] != 0;
            acc[i][j][0] = k0 ? -1e9f : acc[i][j][0] * 0.0625f;
            acc[i][j][1] = k1 ? -1e9f : acc[i][j][1] * 0.0625f;
            acc[i][j][2] = k0 ? -1e9f : acc[i][j][2] * 0.0625f;
            acc[i][j][3] = k1 ? -1e9f : acc[i][j][3] * 0.0625f;
            m0v = fmaxf(m0v, fmaxf(acc[i][j][0], acc[i][j][1]));
            m1v = fmaxf(m1v, fmaxf(acc[i][j][2], acc[i][j][3]));
        }
        m0v = fmaxf(m0v, __shfl_xor_sync(0xffffffff, m0v, 1));
        m0v = fmaxf(m0v, __shfl_xor_sync(0xffffffff, m0v, 2));
        m1v = fmaxf(m1v, __shfl_xor_sync(0xffffffff, m1v, 1));
        m1v = fmaxf(m1v, __shfl_xor_sync(0xffffffff, m1v, 2));
        if (lt == 0) {
            pmax[(mbase + i * 16 + lg) * 4 + wn]     = m0v;
            pmax[(mbase + i * 16 + 8 + lg) * 4 + wn] = m1v;
        }
    }
    __syncthreads();

    float rinv0[4], rinv1[4];
    #pragma unroll
    for (int i = 0; i < 4; i++) {
        int r0 = mbase + i * 16 + lg;
        const float* px0 = pmax + r0 * 4;
        const float* px1 = pmax + (r0 + 8) * 4;
        float g0 = fmaxf(fmaxf(px0[0], px0[1]), fmaxf(px0[2], px0[3]));
        float g1 = fmaxf(fmaxf(px1[0], px1[1]), fmaxf(px1[2], px1[3]));
        float s0 = 0.f, s1 = 0.f;
        #pragma unroll
        for (int j = 0; j < 8; j++) {
            acc[i][j][0] = expf(acc[i][j][0] - g0);
            acc[i][j][1] = expf(acc[i][j][1] - g0);
            acc[i][j][2] = expf(acc[i][j][2] - g1);
            acc[i][j][3] = expf(acc[i][j][3] - g1);
            s0 += acc[i][j][0] + acc[i][j][1];
            s1 += acc[i][j][2] + acc[i][j][3];
        }
        s0 += __shfl_xor_sync(0xffffffff, s0, 1);
        s0 += __shfl_xor_sync(0xffffffff, s0, 2);
        s1 += __shfl_xor_sync(0xffffffff, s1, 1);
        s1 += __shfl_xor_sync(0xffffffff, s1, 2);
        if (lt == 0) {
            psum[r0 * 4 + wn]       = s0;
            psum[(r0 + 8) * 4 + wn] = s1;
        }
    }
    __syncthreads();

    #pragma unroll
    for (int i = 0; i < 4; i++) {
        int r0 = mbase + i * 16 + lg;
        const float* ps0 = psum + r0 * 4;
        const float* ps1 = psum + (r0 + 8) * 4;
        rinv0[i] = 1.0f / (ps0[0] + ps0[1] + ps0[2] + ps0[3]);
        rinv1[i] = 1.0f / (ps1[0] + ps1[1] + ps1[2] + ps1[3]);
        #pragma unroll
        for (int j = 0; j < 8; j++) {
            int c0 = nbase + j * 8 + lt * 2;
            *(__nv_bfloat162*)(Ps + (r0 * 264 + c0)) =
                __floats2bfloat162_rn(acc[i][j][0] * rinv0[i], acc[i][j][1] * rinv0[i]);
            *(__nv_bfloat162*)(Ps + ((r0 + 8) * 264 + c0)) =
                __floats2bfloat162_rn(acc[i][j][2] * rinv1[i], acc[i][j][3] * rinv1[i]);
        }
    }

    #pragma unroll
    for (int i = 0; i < 4; i++)
        #pragma unroll
        for (int j = 0; j < 8; j++)
            #pragma unroll
            for (int r = 0; r < 4; r++) acc[i][j][r] = 0.f;

    for (int it = 0; it < 8; it++) {
        int s = it & 3;
        cp_wait<2>();
        __syncthreads();

        #pragma unroll
        for (int ks = 0; ks < 32; ks += 16) {
            int kg = it * 32 + ks;
            uint32_t a[4][4], bf[8][2];
            #pragma unroll
            for (int i = 0; i < 4; i++) {
                uint32_t addr = sPs + 2u * ((mbase + i * 16 + lr) * 264 + kg + lc8);
                ldsm4(a[i][0], a[i][1], a[i][2], a[i][3], addr);
            }
            #pragma unroll
            for (int jb = 0; jb < 4; jb++) {
                uint32_t r0, r1, r2, r3;
                uint32_t addr = sVs + 2u * ((s * 32 + ks + lr) * 264 + nbase + jb * 16 + lc8);
                ldsm4t(r0, r1, r2, r3, addr);
                bf[jb * 2 + 0][0] = r0; bf[jb * 2 + 0][1] = r1;
                bf[jb * 2 + 1][0] = r2; bf[jb * 2 + 1][1] = r3;
            }
            #pragma unroll
            for (int i = 0; i < 4; i++)
                #pragma unroll
                for (int j = 0; j < 8; j++)
                    mma_bf16(acc[i][j], a[i], bf[j]);
        }

        if (it + 3 < 8) stageV((it + 3) & 3, (it + 3) << 5);
        cp_commit();
    }

    #pragma unroll
    for (int i = 0; i < 4; i++) {
        int r0 = mbase + i * 16 + lg;
        long base0 = (long)(b * SS + m0 + r0) * HD + h * DKH;
        long base1 = (long)(b * SS + m0 + r0 + 8) * HD + h * DKH;
        #pragma unroll
        for (int j = 0; j < 8; j++) {
            int c0 = nbase + j * 8 + lt * 2;
            *(__nv_bfloat162*)(ob + base0 + c0) =
                __floats2bfloat162_rn(acc[i][j][0], acc[i][j][1]);
            *(__nv_bfloat162*)(ob + base1 + c0) =
                __floats2bfloat162_rn(acc[i][j][2], acc[i][j][3]);
        }
    }
}

// ---------------- bf16 HMMA GEMM, BK=64, NST-stage cp.async ---------------
template<int BM, int NST, bool TB>
struct SmemCfg {
    static constexpr int AROW  = 72;
    static constexpr int BROWS = TB ? 128 : 64;
    static constexpr int BCOLS = TB ? 72 : 136;
    static constexpr int A_ELEMS = NST * BM * AROW;
    static constexpr int B_ELEMS = NST * BROWS * BCOLS;
    static constexpr int BYTES = (A_ELEMS + B_ELEMS) * 2;
};

template<int BM, int NST, bool TB, bool RELU, bool RES, bool OUTBF>
__global__ void __launch_bounds__(256)
gemm_bf(const __nv_bfloat16* __restrict__ A, const __nv_bfloat16* __restrict__ B,
        const float* __restrict__ bias, const float* __restrict__ res,
        float* __restrict__ Cf, __nv_bfloat16* __restrict__ Cb,
        int K, int lda, int ldb, int ldc,
        long sAb, long sAh, long sBb, long sBh, long sCb, long sCh)
{
    constexpr int IT = BM / 32;

    extern __shared__ __align__(16) char smem_raw[];
    __nv_bfloat16* As = (__nv_bfloat16*)smem_raw;
    __nv_bfloat16* Bs = As + SmemCfg<BM,NST,TB>::A_ELEMS;

    int z = blockIdx.z;
    int bb = z >> 3, hh = z & 7;
    A += bb * sAb + hh * sAh;
    B += bb * sBb + hh * sBh;
    if (RES) res += bb * sCb + hh * sCh;
    long cbase = bb * sCb + hh * sCh;

    const int m0 = blockIdx.y * BM, n0 = blockIdx.x << 7;
    const int tid  = threadIdx.x;
    const int wid  = tid >> 5;
    const int lane = tid & 31;
    const int mbase = (wid >> 2) * (BM / 2);
    const int nbase = (wid & 3) * 32;
    const int lr  = ((lane >> 3) & 1) * 8 + (lane & 7);
    const int lc8 = (lane >> 4) * 8;

    uint32_t sAs = (uint32_t)__cvta_generic_to_shared(As);
    uint32_t sBs = (uint32_t)__cvta_generic_to_shared(Bs);

    float acc[IT][4][4];
    #pragma unroll
    for (int i = 0; i < IT; i++)
        #pragma unroll
        for (int j = 0; j < 4; j++)
            #pragma unroll
            for (int r = 0; r < 4; r++) acc[i][j][r] = 0.f;

    auto stage = [&](int s, int kb) {
        #pragma unroll
        for (int t = 0; t < BM / 32; t++) {
            int idx = tid + t * 256;
            int row = idx >> 3, ck = idx & 7;
            uint32_t d = sAs + 2u * ((s * BM + row) * 72 + ck * 8);
            cpa16(d, A + (long)(m0 + row) * lda + kb + ck * 8);
        }
        if (!TB) {
            #pragma unroll
            for (int t = 0; t < 4; t++) {
                int idx = tid + t * 256;
                int row = idx >> 4, ck = idx & 15;
                uint32_t d = sBs + 2u * ((s * 64 + row) * 136 + ck * 8);
                cpa16(d, B + (long)(kb + row) * ldb + n0 + ck * 8);
            }
        } else {
            #pragma unroll
            for (int t = 0; t < 4; t++) {
                int idx = tid + t * 256;
                int row = idx >> 3, ck = idx & 7;
                uint32_t d = sBs + 2u * ((s * 128 + row) * 72 + ck * 8);
                cpa16(d, B + (long)(n0 + row) * ldb + kb + ck * 8);
            }
        }
    };

    const int NIT = K >> 6;     // >= 8 at all call sites, > NST-1
    #pragma unroll
    for (int p = 0; p < NST - 1; p++) { stage(p, p << 6); cp_commit(); }

    for (int it = 0; it < NIT; it++) {
        int s = it % NST;
        cp_wait<NST - 2>();
        __syncthreads();

        #pragma unroll
        for (int ks = 0; ks < 64; ks += 16) {
            uint32_t a[IT][4], bf[4][2];
            #pragma unroll
            for (int i = 0; i < IT; i++) {
                uint32_t addr = sAs + 2u * ((s * BM + mbase + i * 16 + lr) * 72 + ks + lc8);
                ldsm4(a[i][0], a[i][1], a[i][2], a[i][3], addr);
            }
            #pragma unroll
            for (int jb = 0; jb < 2; jb++) {
                uint32_t r0, r1, r2, r3;
                if (!TB) {
                    uint32_t addr = sBs + 2u * ((s * 64 + ks + lr) * 136 + nbase + jb * 16 + lc8);
                    ldsm4t(r0, r1, r2, r3, addr);
                    bf[jb * 2 + 0][0] = r0; bf[jb * 2 + 0][1] = r1;
                    bf[jb * 2 + 1][0] = r2; bf[jb * 2 + 1][1] = r3;
                } else {
                    uint32_t addr = sBs + 2u * ((s * 128 + nbase + jb * 16 + lr) * 72 + ks + lc8);
                    ldsm4(r0, r1, r2, r3, addr);
                    bf[jb * 2 + 0][0] = r0; bf[jb * 2 + 0][1] = r2;
                    bf[jb * 2 + 1][0] = r1; bf[jb * 2 + 1][1] = r3;
                }
            }
            #pragma unroll
            for (int i = 0; i < IT; i++)
                #pragma unroll
                for (int j = 0; j < 4; j++)
                    mma_bf16(acc[i][j], a[i], bf[j]);
        }

        // prefetch target (it+NST-1)%NST == (it-1)%NST: its readers finished
        // before the sync at the top of this iteration -> safe to overwrite.
        if (it + NST - 1 < NIT) stage((it + NST - 1) % NST, (it + NST - 1) << 6);
        cp_commit();
    }

    #pragma unroll
    for (int i = 0; i < IT; i++) {
        int r0 = m0 + mbase + i * 16 + (lane >> 2);
        #pragma unroll
        for (int j = 0; j < 4; j++) {
            int c0 = n0 + nbase + j * 8 + (lane & 3) * 2;
            float b0 = 0.f, b1 = 0.f;
            if (bias) { b0 = bias[c0]; b1 = bias[c0 + 1]; }
            float v00 = acc[i][j][0] + b0, v01 = acc[i][j][1] + b1;
            float v10 = acc[i][j][2] + b0, v11 = acc[i][j][3] + b1;
            if (RELU) {
                v00 = fmaxf(v00, 0.f); v01 = fmaxf(v01, 0.f);
                v10 = fmaxf(v10, 0.f); v11 = fmaxf(v11, 0.f);
            }
            if (RES) {
                v00 += res[(long)r0 * ldc + c0];
                v01 += res[(long)r0 * ldc + c0 + 1];
                v10 += res[(long)(r0 + 8) * ldc + c0];
                v11 += res[(long)(r0 + 8) * ldc + c0 + 1];
            }
            if (OUTBF) {
                *(__nv_bfloat162*)(Cb + cbase + (long)r0 * ldc + c0) =
                    __floats2bfloat162_rn(v00, v01);
                *(__nv_bfloat162*)(Cb + cbase + (long)(r0 + 8) * ldc + c0) =
                    __floats2bfloat162_rn(v10, v11);
            } else {
                *(float2*)(Cf + cbase + (long)r0 * ldc + c0)       = make_float2(v00, v01);
                *(float2*)(Cf + cbase + (long)(r0 + 8) * ldc + c0) = make_float2(v10, v11);
            }
        }
    }
}

// ---------------------------------------------------------------------------
extern "C" void kernel_launch(void* const* d_in, const int* in_sizes, int n_in,
                              void* d_out, int out_size)
{
    const float* data    = (const float*)d_in[0];
    const int*   attn_m  = (const int*)  d_in[1];
    const int*   view    = (const int*)  d_in[2];
    const float* seg_emb = (const float*)d_in[3];
    const float* Wq = (const float*)d_in[4];
    const float* bq = (const float*)d_in[5];
    const float* Wk = (const float*)d_in[6];
    const float* bk = (const float*)d_in[7];
    const float* Wv = (const float*)d_in[8];
    const float* bv = (const float*)d_in[9];
    const float* Wo = (const float*)d_in[10];
    const float* bo = (const float*)d_in[11];
    const float* W1 = (const float*)d_in[12];
    const float* b1 = (const float*)d_in[13];
    const float* W2 = (const float*)d_in[14];
    const float* b2 = (const float*)d_in[15];
    const float* alpha1 = (const float*)d_in[16];
    const float* bias1  = (const float*)d_in[17];
    const float* alpha2 = (const float*)d_in[18];
    const float* bias2  = (const float*)d_in[19];
    const float* alpha_f = (const float*)d_in[20];
    const float* bias_f  = (const float*)d_in[21];
    float* out = (float*)d_out;

    float *x;
    __nv_bfloat16 *x2b, *qkv, *ob, *fb;
    __nv_bfloat16 *wqkv, *wo, *w1, *w2;
    float *bqkv;
    cudaGetSymbolAddress((void**)&x,    g_x);
    cudaGetSymbolAddress((void**)&x2b,  g_x2b);
    cudaGetSymbolAddress((void**)&qkv,  g_qkv);
    cudaGetSymbolAddress((void**)&ob,   g_ob);
    cudaGetSymbolAddress((void**)&fb,   g_fb);
    cudaGetSymbolAddress((void**)&wqkv, g_wqkv);
    cudaGetSymbolAddress((void**)&bqkv, g_bqkv);
    cudaGetSymbolAddress((void**)&wo,   g_wo);
    cudaGetSymbolAddress((void**)&w1,   g_w1);
    cudaGetSymbolAddress((void**)&w2,   g_w2);

    constexpr int SM_NN128 = SmemCfg<128,3,false>::BYTES;   // 107520 (3-stage)
    constexpr int SM_NN64  = SmemCfg<64, 4,false>::BYTES;   // 106496 (4-stage)
    cudaFuncSetAttribute(gemm_bf<128,3,false,false,false,true>,
        cudaFuncAttributeMaxDynamicSharedMemorySize, SM_NN128);
    cudaFuncSetAttribute(gemm_bf<128,3,false,true,false,true>,
        cudaFuncAttributeMaxDynamicSharedMemorySize, SM_NN128);
    cudaFuncSetAttribute(gemm_bf<64,4,false,false,true,false>,
        cudaFuncAttributeMaxDynamicSharedMemorySize, SM_NN64);
    cudaFuncSetAttribute(attn_fused,
        cudaFuncAttributeMaxDynamicSharedMemorySize, ATT_SMEM_BYTES);

    cvt_weights<<<(6 * (WSZ / 4)) / 256, 256>>>(Wq, Wk, Wv, Wo, W1, W2);
    cvt_bias<<<(LNUM * QKVN + 255) / 256, 256>>>(bq, bk, bv);
    embed_kernel<<<(TOK * DMODEL + 255) / 256, 256>>>(data, seg_emb, view, x);

    for (int i = 0; i < LNUM; i++) {
        layernorm_kernel<true><<<TOK / 16, 256>>>(x, alpha1 + i * DMODEL, bias1 + i * DMODEL,
                                                  nullptr, x2b);

        // fused QKV: [2048,512] @ [512,6144]  (128x128, 3-stage)
        dim3 gp(QKVN / 128, TOK / 128, 1);
        gemm_bf<128,3,false,false,false,true><<<gp, 256, SM_NN128>>>(
            x2b, wqkv + (long)i * DMODEL * QKVN, bqkv + (long)i * QKVN,
            nullptr, nullptr, qkv, DMODEL, DMODEL, QKVN, QKVN, 0,0,0,0,0,0);

        // fused attention: scores + softmax + PV -> g_ob
        dim3 gs(SS / 128, BB * HEADS);
        attn_fused<<<gs, 256, ATT_SMEM_BYTES>>>(qkv, attn_m, ob);

        // x = x + o @ Wo + bo  (BM=64, 4-stage: K=2048 latency hiding)
        dim3 go(DMODEL / 128, TOK / 64, 1);
        gemm_bf<64,4,false,false,true,false><<<go, 256, SM_NN64>>>(
            ob, wo + (long)i * HD * DMODEL, bo + (long)i * DMODEL,
            x, x, nullptr, HD, HD, DMODEL, DMODEL, 0,0,0,0,0,0);

        layernorm_kernel<true><<<TOK / 16, 256>>>(x, alpha2 + i * DMODEL, bias2 + i * DMODEL,
                                                  nullptr, x2b);

        // ff = relu(x2 @ W1 + b1)  (128x128, 3-stage)
        dim3 gf(DFFN / 128, TOK / 128, 1);
        gemm_bf<128,3,false,true,false,true><<<gf, 256, SM_NN128>>>(
            x2b, w1 + (long)i * DMODEL * DFFN, b1 + (long)i * DFFN,
            nullptr, nullptr, fb, DMODEL, DMODEL, DFFN, DFFN, 0,0,0,0,0,0);

        // x = x + ff @ W2 + b2  (BM=64, 4-stage)
        gemm_bf<64,4,false,false,true,false><<<go, 256, SM_NN64>>>(
            fb, w2 + (long)i * DFFN * DMODEL, b2 + (long)i * DMODEL,
            x, x, nullptr, DFFN, DFFN, DMODEL, DMODEL, 0,0,0,0,0,0);
    }

    layernorm_kernel<false><<<TOK / 16, 256>>>(x, alpha_f, bias_f, out, nullptr);
}